// round 1
// baseline (speedup 1.0000x reference)
#include <cuda_runtime.h>
#include <math.h>

#define LNUM 4
#define DMODEL 512
#define HEADS 8
#define DKH 256
#define DFFN 2048
#define BB 8
#define SS 256
#define HD (HEADS*DKH)          // 2048
#define TOK (BB*SS)             // 2048
#define EPS 1e-6f

// ---------------- scratch (device globals; no allocations) ----------------
__device__ float g_x [TOK*DMODEL];
__device__ float g_x2[TOK*DMODEL];
__device__ float g_q [TOK*HD];
__device__ float g_k [TOK*HD];
__device__ float g_v [TOK*HD];
__device__ float g_s [BB*HEADS*SS*SS];
__device__ float g_o [TOK*HD];
__device__ float g_f [TOK*DFFN];

// ---------------- embed: x = data*sqrt(D) + pe + seg_emb[view*S] ----------
__global__ void embed_kernel(const float* __restrict__ data,
                             const float* __restrict__ seg_emb,
                             const int* __restrict__ view,
                             float* __restrict__ x)
{
    int idx = blockIdx.x * blockDim.x + threadIdx.x;
    if (idx >= TOK * DMODEL) return;
    int c = idx & (DMODEL - 1);
    int s = (idx >> 9) & (SS - 1);
    // S=256=2^8; divisor S^(2c/D) = 2^(c/32) for both even and odd c
    float inv = exp2f(-(float)c * (1.0f / 32.0f));
    float arg = (float)s * inv;
    float pe  = (c & 1) ? cosf(arg) : sinf(arg);
    int seg_off = view[0] * SS * DMODEL + c;
    x[idx] = data[idx] * sqrtf((float)DMODEL) + pe + seg_emb[seg_off];
}

// ---------------- layernorm (unbiased std, (std+eps) denom) ---------------
__global__ void layernorm_kernel(const float* __restrict__ x,
                                 const float* __restrict__ alpha,
                                 const float* __restrict__ beta,
                                 float* __restrict__ out)
{
    int row = blockIdx.x;
    int tid = threadIdx.x;                    // 256 threads, D=512 -> 2 elems
    const float* p = x + (long)row * DMODEL;
    float v0 = p[tid];
    float v1 = p[tid + 256];
    float s  = v0 + v1;
    float sq = v0 * v0 + v1 * v1;

    // warp reduce
    #pragma unroll
    for (int off = 16; off > 0; off >>= 1) {
        s  += __shfl_xor_sync(0xffffffff, s,  off);
        sq += __shfl_xor_sync(0xffffffff, sq, off);
    }
    __shared__ float shs[8], shq[8];
    int wid = tid >> 5, lane = tid & 31;
    if (lane == 0) { shs[wid] = s; shq[wid] = sq; }
    __syncthreads();
    float S = 0.f, SQ = 0.f;
    #pragma unroll
    for (int w = 0; w < 8; w++) { S += shs[w]; SQ += shq[w]; }

    float mean = S * (1.0f / DMODEL);
    float var  = (SQ - (float)DMODEL * mean * mean) * (1.0f / (DMODEL - 1));
    var = fmaxf(var, 0.f);
    float rinv = 1.0f / (sqrtf(var) + EPS);

    float* q = out + (long)row * DMODEL;
    q[tid]       = alpha[tid]       * (v0 - mean) * rinv + beta[tid];
    q[tid + 256] = alpha[tid + 256] * (v1 - mean) * rinv + beta[tid + 256];
}

// ---------------- masked softmax (warp per row of 256) --------------------
__global__ void softmax_kernel(float* __restrict__ sc, const int* __restrict__ attn_m)
{
    int gwarp = (blockIdx.x * blockDim.x + threadIdx.x) >> 5;   // row index
    int lane  = threadIdx.x & 31;
    int b = gwarp >> 11;                                        // / (H*S)
    float* p = sc + (long)gwarp * SS;
    const int* m = attn_m + b * SS;

    float v[8];
    float mx = -1e30f;
    #pragma unroll
    for (int j = 0; j < 8; j++) {
        int t = lane + (j << 5);
        float val = m[t] ? -1e9f : p[t] * 0.0625f;  // 1/sqrt(256)
        v[j] = val;
        mx = fmaxf(mx, val);
    }
    #pragma unroll
    for (int off = 16; off > 0; off >>= 1)
        mx = fmaxf(mx, __shfl_xor_sync(0xffffffff, mx, off));
    float sum = 0.f;
    #pragma unroll
    for (int j = 0; j < 8; j++) { v[j] = expf(v[j] - mx); sum += v[j]; }
    #pragma unroll
    for (int off = 16; off > 0; off >>= 1)
        sum += __shfl_xor_sync(0xffffffff, sum, off);
    float r = 1.0f / sum;
    #pragma unroll
    for (int j = 0; j < 8; j++) p[lane + (j << 5)] = v[j] * r;
}

// ---------------- generic tiled SGEMM 128x128x8, 8x8 microtile ------------
// C[M,N] = A[M,K] @ B(K,N) (+bias[N]) (+relu) (+res).  TB: B stored [N,K].
// Batched via blockIdx.z: b = z>>3, h = z&7; base += b*s?b + h*s?h.
template<bool TB, bool RELU, bool RES>
__global__ void __launch_bounds__(256)
gemm_kernel(const float* __restrict__ A, const float* __restrict__ B,
            const float* __restrict__ bias, const float* __restrict__ res,
            float* __restrict__ C,
            int K, int lda, int ldb, int ldc,
            long sAb, long sAh, long sBb, long sBh, long sCb, long sCh)
{
    int z = blockIdx.z;
    int bb = z >> 3, hh = z & 7;
    A += bb * sAb + hh * sAh;
    B += bb * sBb + hh * sBh;
    C += bb * sCb + hh * sCh;
    if (RES) res += bb * sCb + hh * sCh;

    __shared__ float As[8][128];
    __shared__ float Bs[8][132];

    int m0 = blockIdx.y << 7, n0 = blockIdx.x << 7;
    int tid = threadIdx.x;
    int ty = tid >> 4, tx = tid & 15;

    float acc[8][8];
    #pragma unroll
    for (int i = 0; i < 8; i++)
        #pragma unroll
        for (int j = 0; j < 8; j++) acc[i][j] = 0.f;

    int arow = tid >> 1, acol = (tid & 1) << 2;
    int brow = tid >> 5, bcol = (tid & 31) << 2;

    for (int k0 = 0; k0 < K; k0 += 8) {
        float4 av = *(const float4*)(A + (long)(m0 + arow) * lda + k0 + acol);
        As[acol + 0][arow] = av.x;
        As[acol + 1][arow] = av.y;
        As[acol + 2][arow] = av.z;
        As[acol + 3][arow] = av.w;
        if (!TB) {
            float4 bv = *(const float4*)(B + (long)(k0 + brow) * ldb + n0 + bcol);
            *(float4*)(&Bs[brow][bcol]) = bv;
        } else {
            int j  = tid >> 1;
            int kk = (tid & 1) << 2;
            float4 bv = *(const float4*)(B + (long)(n0 + j) * ldb + k0 + kk);
            Bs[kk + 0][j] = bv.x;
            Bs[kk + 1][j] = bv.y;
            Bs[kk + 2][j] = bv.z;
            Bs[kk + 3][j] = bv.w;
        }
        __syncthreads();

        #pragma unroll
        for (int kk = 0; kk < 8; kk++) {
            float a[8], b[8];
            *(float4*)(a)     = *(const float4*)(&As[kk][ty * 8]);
            *(float4*)(a + 4) = *(const float4*)(&As[kk][ty * 8 + 4]);
            *(float4*)(b)     = *(const float4*)(&Bs[kk][tx * 8]);
            *(float4*)(b + 4) = *(const float4*)(&Bs[kk][tx * 8 + 4]);
            #pragma unroll
            for (int i = 0; i < 8; i++)
                #pragma unroll
                for (int j = 0; j < 8; j++)
                    acc[i][j] += a[i] * b[j];
        }
        __syncthreads();
    }

    #pragma unroll
    for (int i = 0; i < 8; i++) {
        int r = m0 + ty * 8 + i;
        #pragma unroll
        for (int j = 0; j < 8; j++) {
            int c = n0 + tx * 8 + j;
            float vv = acc[i][j];
            if (bias) vv += bias[c];
            if (RELU) vv = fmaxf(vv, 0.f);
            if (RES)  vv += res[(long)r * ldc + c];
            C[(long)r * ldc + c] = vv;
        }
    }
}

// ---------------------------------------------------------------------------
extern "C" void kernel_launch(void* const* d_in, const int* in_sizes, int n_in,
                              void* d_out, int out_size)
{
    const float* data    = (const float*)d_in[0];
    const int*   attn_m  = (const int*)  d_in[1];
    const int*   view    = (const int*)  d_in[2];
    const float* seg_emb = (const float*)d_in[3];
    const float* Wq = (const float*)d_in[4];
    const float* bq = (const float*)d_in[5];
    const float* Wk = (const float*)d_in[6];
    const float* bk = (const float*)d_in[7];
    const float* Wv = (const float*)d_in[8];
    const float* bv = (const float*)d_in[9];
    const float* Wo = (const float*)d_in[10];
    const float* bo = (const float*)d_in[11];
    const float* W1 = (const float*)d_in[12];
    const float* b1 = (const float*)d_in[13];
    const float* W2 = (const float*)d_in[14];
    const float* b2 = (const float*)d_in[15];
    const float* alpha1 = (const float*)d_in[16];
    const float* bias1  = (const float*)d_in[17];
    const float* alpha2 = (const float*)d_in[18];
    const float* bias2  = (const float*)d_in[19];
    const float* alpha_f = (const float*)d_in[20];
    const float* bias_f  = (const float*)d_in[21];
    float* out = (float*)d_out;

    float *x, *x2, *q, *k, *v, *s, *o, *f;
    cudaGetSymbolAddress((void**)&x,  g_x);
    cudaGetSymbolAddress((void**)&x2, g_x2);
    cudaGetSymbolAddress((void**)&q,  g_q);
    cudaGetSymbolAddress((void**)&k,  g_k);
    cudaGetSymbolAddress((void**)&v,  g_v);
    cudaGetSymbolAddress((void**)&s,  g_s);
    cudaGetSymbolAddress((void**)&o,  g_o);
    cudaGetSymbolAddress((void**)&f,  g_f);

    embed_kernel<<<(TOK * DMODEL + 255) / 256, 256>>>(data, seg_emb, view, x);

    const long sBH = (long)SS * HD;   // per-b stride in q/k/v/o
    const long sHH = DKH;             // per-h stride
    const long sSB = 8L * SS * SS;    // scores per-b
    const long sSH = (long)SS * SS;   // scores per-h

    for (int i = 0; i < LNUM; i++) {
        layernorm_kernel<<<TOK, 256>>>(x, alpha1 + i * DMODEL, bias1 + i * DMODEL, x2);

        // Q,K,V projections: [2048,512] @ [512,2048]
        dim3 gp(HD / 128, TOK / 128, 1);
        gemm_kernel<false,false,false><<<gp, 256>>>(x2, Wq + (long)i * DMODEL * HD,
            bq + (long)i * HD, nullptr, q, DMODEL, DMODEL, HD, HD, 0,0,0,0,0,0);
        gemm_kernel<false,false,false><<<gp, 256>>>(x2, Wk + (long)i * DMODEL * HD,
            bk + (long)i * HD, nullptr, k, DMODEL, DMODEL, HD, HD, 0,0,0,0,0,0);
        gemm_kernel<false,false,false><<<gp, 256>>>(x2, Wv + (long)i * DMODEL * HD,
            bv + (long)i * HD, nullptr, v, DMODEL, DMODEL, HD, HD, 0,0,0,0,0,0);

        // scores = q @ k^T  (batched over 64 heads), NT
        dim3 ga(SS / 128, SS / 128, BB * HEADS);
        gemm_kernel<true,false,false><<<ga, 256>>>(q, k, nullptr, nullptr, s,
            DKH, HD, HD, SS, sBH, sHH, sBH, sHH, sSB, sSH);

        softmax_kernel<<<(BB * HEADS * SS) / 8, 256>>>(s, attn_m);

        // o = attnw @ v (batched), NN
        dim3 gv(DKH / 128, SS / 128, BB * HEADS);
        gemm_kernel<false,false,false><<<gv, 256>>>(s, v, nullptr, nullptr, o,
            SS, SS, HD, HD, sSB, sSH, sBH, sHH, sBH, sHH);

        // x = x + o @ Wo + bo
        dim3 go(DMODEL / 128, TOK / 128, 1);
        gemm_kernel<false,false,true><<<go, 256>>>(o, Wo + (long)i * HD * DMODEL,
            bo + (long)i * DMODEL, x, x, HD, HD, DMODEL, DMODEL, 0,0,0,0,0,0);

        layernorm_kernel<<<TOK, 256>>>(x, alpha2 + i * DMODEL, bias2 + i * DMODEL, x2);

        // ff = relu(x2 @ W1 + b1)
        dim3 gf(DFFN / 128, TOK / 128, 1);
        gemm_kernel<false,true,false><<<gf, 256>>>(x2, W1 + (long)i * DMODEL * DFFN,
            b1 + (long)i * DFFN, nullptr, f, DMODEL, DMODEL, DFFN, DFFN, 0,0,0,0,0,0);

        // x = x + ff @ W2 + b2
        gemm_kernel<false,false,true><<<go, 256>>>(f, W2 + (long)i * DFFN * DMODEL,
            b2 + (long)i * DMODEL, x, x, DFFN, DFFN, DMODEL, DMODEL, 0,0,0,0,0,0);
    }

    layernorm_kernel<<<TOK, 256>>>(x, alpha_f, bias_f, out);
}

// round 2
// speedup vs baseline: 3.1675x; 3.1675x over previous
#include <cuda_runtime.h>
#include <math.h>
#include <stdint.h>

#define LNUM 4
#define DMODEL 512
#define HEADS 8
#define DKH 256
#define DFFN 2048
#define BB 8
#define SS 256
#define HD (HEADS*DKH)          // 2048
#define TOK (BB*SS)             // 2048
#define EPS 1e-6f

// ---------------- scratch (device globals; no allocations) ----------------
__device__ float g_x [TOK*DMODEL];
__device__ float g_x2[TOK*DMODEL];
__device__ float g_q [TOK*HD];
__device__ float g_k [TOK*HD];
__device__ float g_v [TOK*HD];
__device__ float g_s [BB*HEADS*SS*SS];
__device__ float g_o [TOK*HD];
__device__ float g_f [TOK*DFFN];

__device__ __forceinline__ uint32_t f2tf32(float x) {
    uint32_t y;
    asm("cvt.rna.tf32.f32 %0, %1;" : "=r"(y) : "f"(x));
    return y;
}

// ---------------- embed: x = data*sqrt(D) + pe + seg_emb[view*S] ----------
__global__ void embed_kernel(const float* __restrict__ data,
                             const float* __restrict__ seg_emb,
                             const int* __restrict__ view,
                             float* __restrict__ x)
{
    int idx = blockIdx.x * blockDim.x + threadIdx.x;
    if (idx >= TOK * DMODEL) return;
    int c = idx & (DMODEL - 1);
    int s = (idx >> 9) & (SS - 1);
    float inv = exp2f(-(float)c * (1.0f / 32.0f));
    float arg = (float)s * inv;
    float pe  = (c & 1) ? cosf(arg) : sinf(arg);
    int seg_off = view[0] * SS * DMODEL + c;
    x[idx] = data[idx] * sqrtf((float)DMODEL) + pe + seg_emb[seg_off];
}

// ---------------- layernorm (unbiased std, (std+eps) denom) ---------------
__global__ void layernorm_kernel(const float* __restrict__ x,
                                 const float* __restrict__ alpha,
                                 const float* __restrict__ beta,
                                 float* __restrict__ out)
{
    int row = blockIdx.x;
    int tid = threadIdx.x;
    const float* p = x + (long)row * DMODEL;
    float v0 = p[tid];
    float v1 = p[tid + 256];
    float s  = v0 + v1;
    float sq = v0 * v0 + v1 * v1;

    #pragma unroll
    for (int off = 16; off > 0; off >>= 1) {
        s  += __shfl_xor_sync(0xffffffff, s,  off);
        sq += __shfl_xor_sync(0xffffffff, sq, off);
    }
    __shared__ float shs[8], shq[8];
    int wid = tid >> 5, lane = tid & 31;
    if (lane == 0) { shs[wid] = s; shq[wid] = sq; }
    __syncthreads();
    float S = 0.f, SQ = 0.f;
    #pragma unroll
    for (int w = 0; w < 8; w++) { S += shs[w]; SQ += shq[w]; }

    float mean = S * (1.0f / DMODEL);
    float var  = (SQ - (float)DMODEL * mean * mean) * (1.0f / (DMODEL - 1));
    var = fmaxf(var, 0.f);
    float rinv = 1.0f / (sqrtf(var) + EPS);

    float* q = out + (long)row * DMODEL;
    q[tid]       = alpha[tid]       * (v0 - mean) * rinv + beta[tid];
    q[tid + 256] = alpha[tid + 256] * (v1 - mean) * rinv + beta[tid + 256];
}

// ---------------- masked softmax (warp per row of 256) --------------------
__global__ void softmax_kernel(float* __restrict__ sc, const int* __restrict__ attn_m)
{
    int gwarp = (blockIdx.x * blockDim.x + threadIdx.x) >> 5;
    int lane  = threadIdx.x & 31;
    int b = gwarp >> 11;
    float* p = sc + (long)gwarp * SS;
    const int* m = attn_m + b * SS;

    float v[8];
    float mx = -1e30f;
    #pragma unroll
    for (int j = 0; j < 8; j++) {
        int t = lane + (j << 5);
        float val = m[t] ? -1e9f : p[t] * 0.0625f;
        v[j] = val;
        mx = fmaxf(mx, val);
    }
    #pragma unroll
    for (int off = 16; off > 0; off >>= 1)
        mx = fmaxf(mx, __shfl_xor_sync(0xffffffff, mx, off));
    float sum = 0.f;
    #pragma unroll
    for (int j = 0; j < 8; j++) { v[j] = expf(v[j] - mx); sum += v[j]; }
    #pragma unroll
    for (int off = 16; off > 0; off >>= 1)
        sum += __shfl_xor_sync(0xffffffff, sum, off);
    float r = 1.0f / sum;
    #pragma unroll
    for (int j = 0; j < 8; j++) p[lane + (j << 5)] = v[j] * r;
}

// ---------------- TF32 tensor-core GEMM 128x128x16 ------------------------
// C[M,N] = A[M,K] @ B(K,N) (+bias) (+relu) (+res).  TB: B stored [N,K].
// 256 threads = 8 warps (2 M x 4 N), warp tile 64x32, mma m16n8k8 tf32.
template<bool TB, bool RELU, bool RES>
__global__ void __launch_bounds__(256)
gemm_tc(const float* __restrict__ A, const float* __restrict__ B,
        const float* __restrict__ bias, const float* __restrict__ res,
        float* __restrict__ C,
        int K, int lda, int ldb, int ldc,
        long sAb, long sAh, long sBb, long sBh, long sCb, long sCh)
{
    int z = blockIdx.z;
    int bb = z >> 3, hh = z & 7;
    A += bb * sAb + hh * sAh;
    B += bb * sBb + hh * sBh;
    C += bb * sCb + hh * sCh;
    if (RES) res += bb * sCb + hh * sCh;

    __shared__ uint32_t As[128][20];   // [m][k], pad 20 -> conflict-free frags
    __shared__ uint32_t Bs[16][136];   // [k][n], pad 136

    const int m0 = blockIdx.y << 7, n0 = blockIdx.x << 7;
    const int tid  = threadIdx.x;
    const int wid  = tid >> 5;
    const int lane = tid & 31;
    const int mbase = (wid >> 2) * 64;   // warp m offset (0/64)
    const int nbase = (wid & 3) * 32;    // warp n offset
    const int lg = lane >> 2;            // groupID 0..7
    const int lt = lane & 3;             // thread-in-group 0..3

    float acc[4][4][4];
    #pragma unroll
    for (int i = 0; i < 4; i++)
        #pragma unroll
        for (int j = 0; j < 4; j++)
            #pragma unroll
            for (int r = 0; r < 4; r++) acc[i][j][r] = 0.f;

    // global tile load indices
    const int ar  = tid >> 2;            // 0..63
    const int ac4 = (tid & 3) << 2;      // 0,4,8,12
    const int br  = tid >> 5;            // 0..7  (NN)
    const int bc4 = (tid & 31) << 2;     // 0..124 (NN)
    const int tn  = tid >> 2;            // 0..63 (NT)
    const int tk4 = (tid & 3) << 2;      // (NT)

    float4 pa0, pa1, pb0, pb1;

    // prologue: load k0 = 0
    pa0 = *(const float4*)(A + (long)(m0 + ar)      * lda + ac4);
    pa1 = *(const float4*)(A + (long)(m0 + ar + 64) * lda + ac4);
    if (!TB) {
        pb0 = *(const float4*)(B + (long)(br)     * ldb + n0 + bc4);
        pb1 = *(const float4*)(B + (long)(br + 8) * ldb + n0 + bc4);
    } else {
        pb0 = *(const float4*)(B + (long)(n0 + tn)      * ldb + tk4);
        pb1 = *(const float4*)(B + (long)(n0 + tn + 64) * ldb + tk4);
    }

    for (int k0 = 0; k0 < K; k0 += 16) {
        // stage current tile into smem (tf32-rounded)
        {
            uint4 sa0 = { f2tf32(pa0.x), f2tf32(pa0.y), f2tf32(pa0.z), f2tf32(pa0.w) };
            uint4 sa1 = { f2tf32(pa1.x), f2tf32(pa1.y), f2tf32(pa1.z), f2tf32(pa1.w) };
            *(uint4*)(&As[ar][ac4])      = sa0;
            *(uint4*)(&As[ar + 64][ac4]) = sa1;
            if (!TB) {
                uint4 sb0 = { f2tf32(pb0.x), f2tf32(pb0.y), f2tf32(pb0.z), f2tf32(pb0.w) };
                uint4 sb1 = { f2tf32(pb1.x), f2tf32(pb1.y), f2tf32(pb1.z), f2tf32(pb1.w) };
                *(uint4*)(&Bs[br][bc4])     = sb0;
                *(uint4*)(&Bs[br + 8][bc4]) = sb1;
            } else {
                Bs[tk4 + 0][tn] = f2tf32(pb0.x);
                Bs[tk4 + 1][tn] = f2tf32(pb0.y);
                Bs[tk4 + 2][tn] = f2tf32(pb0.z);
                Bs[tk4 + 3][tn] = f2tf32(pb0.w);
                Bs[tk4 + 0][tn + 64] = f2tf32(pb1.x);
                Bs[tk4 + 1][tn + 64] = f2tf32(pb1.y);
                Bs[tk4 + 2][tn + 64] = f2tf32(pb1.z);
                Bs[tk4 + 3][tn + 64] = f2tf32(pb1.w);
            }
        }
        __syncthreads();

        // prefetch next tile (global -> regs)
        bool has_next = (k0 + 16) < K;
        if (has_next) {
            int kn = k0 + 16;
            pa0 = *(const float4*)(A + (long)(m0 + ar)      * lda + kn + ac4);
            pa1 = *(const float4*)(A + (long)(m0 + ar + 64) * lda + kn + ac4);
            if (!TB) {
                pb0 = *(const float4*)(B + (long)(kn + br)     * ldb + n0 + bc4);
                pb1 = *(const float4*)(B + (long)(kn + br + 8) * ldb + n0 + bc4);
            } else {
                pb0 = *(const float4*)(B + (long)(n0 + tn)      * ldb + kn + tk4);
                pb1 = *(const float4*)(B + (long)(n0 + tn + 64) * ldb + kn + tk4);
            }
        }

        // compute 2 k-steps of 8
        #pragma unroll
        for (int ks = 0; ks < 2; ks++) {
            const int kb = ks * 8;
            uint32_t a[4][4], b[4][2];
            #pragma unroll
            for (int i = 0; i < 4; i++) {
                int r = mbase + i * 16 + lg;
                a[i][0] = As[r][kb + lt];
                a[i][1] = As[r + 8][kb + lt];
                a[i][2] = As[r][kb + lt + 4];
                a[i][3] = As[r + 8][kb + lt + 4];
            }
            #pragma unroll
            for (int j = 0; j < 4; j++) {
                int c = nbase + j * 8 + lg;
                b[j][0] = Bs[kb + lt][c];
                b[j][1] = Bs[kb + lt + 4][c];
            }
            #pragma unroll
            for (int i = 0; i < 4; i++)
                #pragma unroll
                for (int j = 0; j < 4; j++) {
                    asm volatile(
                        "mma.sync.aligned.m16n8k8.row.col.f32.tf32.tf32.f32 "
                        "{%0,%1,%2,%3}, {%4,%5,%6,%7}, {%8,%9}, {%0,%1,%2,%3};"
                        : "+f"(acc[i][j][0]), "+f"(acc[i][j][1]),
                          "+f"(acc[i][j][2]), "+f"(acc[i][j][3])
                        : "r"(a[i][0]), "r"(a[i][1]), "r"(a[i][2]), "r"(a[i][3]),
                          "r"(b[j][0]), "r"(b[j][1]));
                }
        }
        __syncthreads();
    }

    // epilogue
    #pragma unroll
    for (int i = 0; i < 4; i++) {
        int r0 = m0 + mbase + i * 16 + lg;
        #pragma unroll
        for (int j = 0; j < 4; j++) {
            int c0 = n0 + nbase + j * 8 + lt * 2;
            float b0 = 0.f, b1 = 0.f;
            if (bias) { b0 = bias[c0]; b1 = bias[c0 + 1]; }
            float v00 = acc[i][j][0] + b0, v01 = acc[i][j][1] + b1;
            float v10 = acc[i][j][2] + b0, v11 = acc[i][j][3] + b1;
            if (RELU) {
                v00 = fmaxf(v00, 0.f); v01 = fmaxf(v01, 0.f);
                v10 = fmaxf(v10, 0.f); v11 = fmaxf(v11, 0.f);
            }
            if (RES) {
                v00 += res[(long)r0 * ldc + c0];
                v01 += res[(long)r0 * ldc + c0 + 1];
                v10 += res[(long)(r0 + 8) * ldc + c0];
                v11 += res[(long)(r0 + 8) * ldc + c0 + 1];
            }
            *(float2*)(C + (long)r0 * ldc + c0)       = make_float2(v00, v01);
            *(float2*)(C + (long)(r0 + 8) * ldc + c0) = make_float2(v10, v11);
        }
    }
}

// ---------------------------------------------------------------------------
extern "C" void kernel_launch(void* const* d_in, const int* in_sizes, int n_in,
                              void* d_out, int out_size)
{
    const float* data    = (const float*)d_in[0];
    const int*   attn_m  = (const int*)  d_in[1];
    const int*   view    = (const int*)  d_in[2];
    const float* seg_emb = (const float*)d_in[3];
    const float* Wq = (const float*)d_in[4];
    const float* bq = (const float*)d_in[5];
    const float* Wk = (const float*)d_in[6];
    const float* bk = (const float*)d_in[7];
    const float* Wv = (const float*)d_in[8];
    const float* bv = (const float*)d_in[9];
    const float* Wo = (const float*)d_in[10];
    const float* bo = (const float*)d_in[11];
    const float* W1 = (const float*)d_in[12];
    const float* b1 = (const float*)d_in[13];
    const float* W2 = (const float*)d_in[14];
    const float* b2 = (const float*)d_in[15];
    const float* alpha1 = (const float*)d_in[16];
    const float* bias1  = (const float*)d_in[17];
    const float* alpha2 = (const float*)d_in[18];
    const float* bias2  = (const float*)d_in[19];
    const float* alpha_f = (const float*)d_in[20];
    const float* bias_f  = (const float*)d_in[21];
    float* out = (float*)d_out;

    float *x, *x2, *q, *k, *v, *s, *o, *f;
    cudaGetSymbolAddress((void**)&x,  g_x);
    cudaGetSymbolAddress((void**)&x2, g_x2);
    cudaGetSymbolAddress((void**)&q,  g_q);
    cudaGetSymbolAddress((void**)&k,  g_k);
    cudaGetSymbolAddress((void**)&v,  g_v);
    cudaGetSymbolAddress((void**)&s,  g_s);
    cudaGetSymbolAddress((void**)&o,  g_o);
    cudaGetSymbolAddress((void**)&f,  g_f);

    embed_kernel<<<(TOK * DMODEL + 255) / 256, 256>>>(data, seg_emb, view, x);

    const long sBH = (long)SS * HD;
    const long sHH = DKH;
    const long sSB = 8L * SS * SS;
    const long sSH = (long)SS * SS;

    for (int i = 0; i < LNUM; i++) {
        layernorm_kernel<<<TOK, 256>>>(x, alpha1 + i * DMODEL, bias1 + i * DMODEL, x2);

        dim3 gp(HD / 128, TOK / 128, 1);
        gemm_tc<false,false,false><<<gp, 256>>>(x2, Wq + (long)i * DMODEL * HD,
            bq + (long)i * HD, nullptr, q, DMODEL, DMODEL, HD, HD, 0,0,0,0,0,0);
        gemm_tc<false,false,false><<<gp, 256>>>(x2, Wk + (long)i * DMODEL * HD,
            bk + (long)i * HD, nullptr, k, DMODEL, DMODEL, HD, HD, 0,0,0,0,0,0);
        gemm_tc<false,false,false><<<gp, 256>>>(x2, Wv + (long)i * DMODEL * HD,
            bv + (long)i * HD, nullptr, v, DMODEL, DMODEL, HD, HD, 0,0,0,0,0,0);

        dim3 ga(SS / 128, SS / 128, BB * HEADS);
        gemm_tc<true,false,false><<<ga, 256>>>(q, k, nullptr, nullptr, s,
            DKH, HD, HD, SS, sBH, sHH, sBH, sHH, sSB, sSH);

        softmax_kernel<<<(BB * HEADS * SS) / 8, 256>>>(s, attn_m);

        dim3 gv(DKH / 128, SS / 128, BB * HEADS);
        gemm_tc<false,false,false><<<gv, 256>>>(s, v, nullptr, nullptr, o,
            SS, SS, HD, HD, sSB, sSH, sBH, sHH, sBH, sHH);

        dim3 go(DMODEL / 128, TOK / 128, 1);
        gemm_tc<false,false,true><<<go, 256>>>(o, Wo + (long)i * HD * DMODEL,
            bo + (long)i * DMODEL, x, x, HD, HD, DMODEL, DMODEL, 0,0,0,0,0,0);

        layernorm_kernel<<<TOK, 256>>>(x, alpha2 + i * DMODEL, bias2 + i * DMODEL, x2);

        dim3 gf(DFFN / 128, TOK / 128, 1);
        gemm_tc<false,true,false><<<gf, 256>>>(x2, W1 + (long)i * DMODEL * DFFN,
            b1 + (long)i * DFFN, nullptr, f, DMODEL, DMODEL, DFFN, DFFN, 0,0,0,0,0,0);

        gemm_tc<false,false,true><<<go, 256>>>(f, W2 + (long)i * DFFN * DMODEL,
            b2 + (long)i * DMODEL, x, x, DFFN, DFFN, DMODEL, DMODEL, 0,0,0,0,0,0);
    }

    layernorm_kernel<<<TOK, 256>>>(x, alpha_f, bias_f, out);
}

// round 4
// speedup vs baseline: 6.0384x; 1.9063x over previous
#include <cuda_runtime.h>
#include <cuda_bf16.h>
#include <math.h>
#include <stdint.h>

#define LNUM 4
#define DMODEL 512
#define HEADS 8
#define DKH 256
#define DFFN 2048
#define BB 8
#define SS 256
#define HD (HEADS*DKH)          // 2048
#define TOK (BB*SS)             // 2048
#define EPS 1e-6f

// ---------------- scratch (device globals; no allocations) ----------------
__device__ float g_x [TOK*DMODEL];          // fp32 residual stream
__device__ float g_s [BB*HEADS*SS*SS];      // fp32 attention logits

__device__ __nv_bfloat16 g_x2b[TOK*DMODEL];
__device__ __nv_bfloat16 g_qb [TOK*HD];
__device__ __nv_bfloat16 g_kb [TOK*HD];
__device__ __nv_bfloat16 g_vb [TOK*HD];
__device__ __nv_bfloat16 g_sb [BB*HEADS*SS*SS];
__device__ __nv_bfloat16 g_ob [TOK*HD];
__device__ __nv_bfloat16 g_fb [TOK*DFFN];
// bf16 weights (each 4*512*2048 = 4194304 elems)
#define WSZ 4194304
__device__ __nv_bfloat16 g_wq[WSZ];
__device__ __nv_bfloat16 g_wk[WSZ];
__device__ __nv_bfloat16 g_wv[WSZ];
__device__ __nv_bfloat16 g_wo[WSZ];
__device__ __nv_bfloat16 g_w1[WSZ];
__device__ __nv_bfloat16 g_w2[WSZ];

// ---------------- PTX helpers ---------------------------------------------
__device__ __forceinline__ void cpa16(uint32_t dst, const void* src) {
    asm volatile("cp.async.cg.shared.global [%0], [%1], 16;" :: "r"(dst), "l"(src) : "memory");
}
__device__ __forceinline__ void cp_commit() {
    asm volatile("cp.async.commit_group;" ::: "memory");
}
__device__ __forceinline__ void cp_wait0() {
    asm volatile("cp.async.wait_group 0;" ::: "memory");
}
__device__ __forceinline__ void ldsm4(uint32_t& r0, uint32_t& r1, uint32_t& r2, uint32_t& r3, uint32_t a) {
    asm volatile("ldmatrix.sync.aligned.m8n8.x4.shared.b16 {%0,%1,%2,%3}, [%4];"
                 : "=r"(r0), "=r"(r1), "=r"(r2), "=r"(r3) : "r"(a));
}
__device__ __forceinline__ void ldsm4t(uint32_t& r0, uint32_t& r1, uint32_t& r2, uint32_t& r3, uint32_t a) {
    asm volatile("ldmatrix.sync.aligned.m8n8.x4.trans.shared.b16 {%0,%1,%2,%3}, [%4];"
                 : "=r"(r0), "=r"(r1), "=r"(r2), "=r"(r3) : "r"(a));
}
__device__ __forceinline__ void mma_bf16(float* d, const uint32_t* a, const uint32_t* b) {
    asm volatile("mma.sync.aligned.m16n8k16.row.col.f32.bf16.bf16.f32 "
                 "{%0,%1,%2,%3}, {%4,%5,%6,%7}, {%8,%9}, {%0,%1,%2,%3};"
                 : "+f"(d[0]), "+f"(d[1]), "+f"(d[2]), "+f"(d[3])
                 : "r"(a[0]), "r"(a[1]), "r"(a[2]), "r"(a[3]), "r"(b[0]), "r"(b[1]));
}

// ---------------- weight fp32 -> bf16 (once per launch) -------------------
__global__ void cvt_weights(const float* __restrict__ wq, const float* __restrict__ wk,
                            const float* __restrict__ wv, const float* __restrict__ wo,
                            const float* __restrict__ w1, const float* __restrict__ w2)
{
    long i4 = (long)blockIdx.x * blockDim.x + threadIdx.x;   // 6 * 2^20 threads
    int which = (int)(i4 >> 20);
    long off = (i4 & ((1L << 20) - 1)) << 2;
    const float* s;
    __nv_bfloat16* d;
    switch (which) {
        case 0: s = wq; d = g_wq; break;
        case 1: s = wk; d = g_wk; break;
        case 2: s = wv; d = g_wv; break;
        case 3: s = wo; d = g_wo; break;
        case 4: s = w1; d = g_w1; break;
        default: s = w2; d = g_w2; break;
    }
    float4 v = *(const float4*)(s + off);
    __nv_bfloat162 p0 = __floats2bfloat162_rn(v.x, v.y);
    __nv_bfloat162 p1 = __floats2bfloat162_rn(v.z, v.w);
    *(__nv_bfloat162*)(d + off)     = p0;
    *(__nv_bfloat162*)(d + off + 2) = p1;
}

// ---------------- embed ----------------------------------------------------
__global__ void embed_kernel(const float* __restrict__ data,
                             const float* __restrict__ seg_emb,
                             const int* __restrict__ view,
                             float* __restrict__ x)
{
    int idx = blockIdx.x * blockDim.x + threadIdx.x;
    if (idx >= TOK * DMODEL) return;
    int c = idx & (DMODEL - 1);
    int s = (idx >> 9) & (SS - 1);
    float inv = exp2f(-(float)c * (1.0f / 32.0f));
    float arg = (float)s * inv;
    float pe  = (c & 1) ? cosf(arg) : sinf(arg);
    int seg_off = view[0] * SS * DMODEL + c;
    x[idx] = data[idx] * sqrtf((float)DMODEL) + pe + seg_emb[seg_off];
}

// ---------------- layernorm: fp32 in, bf16 (or fp32) out ------------------
template<bool OB>
__global__ void layernorm_kernel(const float* __restrict__ x,
                                 const float* __restrict__ alpha,
                                 const float* __restrict__ beta,
                                 float* __restrict__ outf,
                                 __nv_bfloat16* __restrict__ outb)
{
    int row = blockIdx.x;
    int tid = threadIdx.x;
    const float* p = x + (long)row * DMODEL;
    float v0 = p[tid];
    float v1 = p[tid + 256];
    float s  = v0 + v1;
    float sq = v0 * v0 + v1 * v1;

    #pragma unroll
    for (int off = 16; off > 0; off >>= 1) {
        s  += __shfl_xor_sync(0xffffffff, s,  off);
        sq += __shfl_xor_sync(0xffffffff, sq, off);
    }
    __shared__ float shs[8], shq[8];
    int wid = tid >> 5, lane = tid & 31;
    if (lane == 0) { shs[wid] = s; shq[wid] = sq; }
    __syncthreads();
    float S = 0.f, SQ = 0.f;
    #pragma unroll
    for (int w = 0; w < 8; w++) { S += shs[w]; SQ += shq[w]; }

    float mean = S * (1.0f / DMODEL);
    float var  = (SQ - (float)DMODEL * mean * mean) * (1.0f / (DMODEL - 1));
    var = fmaxf(var, 0.f);
    float rinv = 1.0f / (sqrtf(var) + EPS);

    float o0 = alpha[tid]       * (v0 - mean) * rinv + beta[tid];
    float o1 = alpha[tid + 256] * (v1 - mean) * rinv + beta[tid + 256];
    if (OB) {
        outb[(long)row * DMODEL + tid]       = __float2bfloat16(o0);
        outb[(long)row * DMODEL + tid + 256] = __float2bfloat16(o1);
    } else {
        outf[(long)row * DMODEL + tid]       = o0;
        outf[(long)row * DMODEL + tid + 256] = o1;
    }
}

// ---------------- masked softmax: fp32 logits in, bf16 probs out ----------
__global__ void softmax_kernel(const float* __restrict__ sc,
                               __nv_bfloat16* __restrict__ sb,
                               const int* __restrict__ attn_m)
{
    int gwarp = (blockIdx.x * blockDim.x + threadIdx.x) >> 5;
    int lane  = threadIdx.x & 31;
    int b = gwarp >> 11;
    const float* p = sc + (long)gwarp * SS;
    __nv_bfloat16* q = sb + (long)gwarp * SS;
    const int* m = attn_m + b * SS;

    float v[8];
    float mx = -1e30f;
    #pragma unroll
    for (int j = 0; j < 8; j++) {
        int t = lane + (j << 5);
        float val = m[t] ? -1e9f : p[t] * 0.0625f;
        v[j] = val;
        mx = fmaxf(mx, val);
    }
    #pragma unroll
    for (int off = 16; off > 0; off >>= 1)
        mx = fmaxf(mx, __shfl_xor_sync(0xffffffff, mx, off));
    float sum = 0.f;
    #pragma unroll
    for (int j = 0; j < 8; j++) { v[j] = expf(v[j] - mx); sum += v[j]; }
    #pragma unroll
    for (int off = 16; off > 0; off >>= 1)
        sum += __shfl_xor_sync(0xffffffff, sum, off);
    float r = 1.0f / sum;
    #pragma unroll
    for (int j = 0; j < 8; j++) q[lane + (j << 5)] = __float2bfloat16(v[j] * r);
}

// ---------------- bf16 tensor-core GEMM, cp.async pipeline ----------------
// C[M,N]=A[M,K]@B(K,N) (+bias)(+relu)(+res). TB: B stored [N,K].
// CTA: BM x 128 x 32.  8 warps (2 M x 4 N).  mma m16n8k16 bf16, fp32 acc.
template<int BM, bool TB, bool RELU, bool RES, bool OUTBF>
__global__ void __launch_bounds__(256)
gemm_bf(const __nv_bfloat16* __restrict__ A, const __nv_bfloat16* __restrict__ B,
        const float* __restrict__ bias, const float* __restrict__ res,
        float* __restrict__ Cf, __nv_bfloat16* __restrict__ Cb,
        int K, int lda, int ldb, int ldc,
        long sAb, long sAh, long sBb, long sBh, long sCb, long sCh)
{
    constexpr int IT = BM / 32;                 // i-tiles per warp
    constexpr int BROWS = TB ? 128 : 32;
    constexpr int BCOLS = TB ? 40 : 136;

    __shared__ __align__(16) __nv_bfloat16 As[2][BM][40];
    __shared__ __align__(16) __nv_bfloat16 Bs[2][BROWS][BCOLS];

    int z = blockIdx.z;
    int bb = z >> 3, hh = z & 7;
    A += bb * sAb + hh * sAh;
    B += bb * sBb + hh * sBh;
    if (RES) res += bb * sCb + hh * sCh;
    long cbase = bb * sCb + hh * sCh;

    const int m0 = blockIdx.y * BM, n0 = blockIdx.x << 7;
    const int tid  = threadIdx.x;
    const int wid  = tid >> 5;
    const int lane = tid & 31;
    const int mbase = (wid >> 2) * (BM / 2);
    const int nbase = (wid & 3) * 32;
    const int lr  = ((lane >> 3) & 1) * 8 + (lane & 7);   // ldmatrix row-in-16
    const int lc8 = (lane >> 4) * 8;                      // ldmatrix col 8-off

    uint32_t sAs = (uint32_t)__cvta_generic_to_shared(&As[0][0][0]);
    uint32_t sBs = (uint32_t)__cvta_generic_to_shared(&Bs[0][0][0]);

    float acc[IT][4][4];
    #pragma unroll
    for (int i = 0; i < IT; i++)
        #pragma unroll
        for (int j = 0; j < 4; j++)
            #pragma unroll
            for (int r = 0; r < 4; r++) acc[i][j][r] = 0.f;

    auto stage = [&](int s, int kb) {
        #pragma unroll
        for (int t = 0; t < BM / 64; t++) {           // A: BM*4 16B chunks
            int idx = tid + t * 256;
            int row = idx >> 2, ck = idx & 3;
            uint32_t d = sAs + 2u * ((s * BM + row) * 40 + ck * 8);
            cpa16(d, A + (long)(m0 + row) * lda + kb + ck * 8);
        }
        if (!TB) {
            #pragma unroll
            for (int t = 0; t < 2; t++) {             // B: 32 x 128
                int idx = tid + t * 256;
                int row = idx >> 4, ck = idx & 15;
                uint32_t d = sBs + 2u * ((s * 32 + row) * 136 + ck * 8);
                cpa16(d, B + (long)(kb + row) * ldb + n0 + ck * 8);
            }
        } else {
            #pragma unroll
            for (int t = 0; t < 2; t++) {             // B: 128 n-rows x 32 k
                int idx = tid + t * 256;
                int row = idx >> 2, ck = idx & 3;
                uint32_t d = sBs + 2u * ((s * 128 + row) * 40 + ck * 8);
                cpa16(d, B + (long)(n0 + row) * ldb + kb + ck * 8);
            }
        }
    };

    const int NIT = K >> 5;
    stage(0, 0);
    cp_commit();

    for (int it = 0; it < NIT; it++) {
        cp_wait0();
        __syncthreads();
        if (it + 1 < NIT) { stage((it + 1) & 1, (it + 1) << 5); cp_commit(); }
        int s = it & 1;

        #pragma unroll
        for (int ks = 0; ks < 32; ks += 16) {
            uint32_t a[IT][4], bf[4][2];
            #pragma unroll
            for (int i = 0; i < IT; i++) {
                uint32_t addr = sAs + 2u * ((s * BM + mbase + i * 16 + lr) * 40 + ks + lc8);
                ldsm4(a[i][0], a[i][1], a[i][2], a[i][3], addr);
            }
            #pragma unroll
            for (int jb = 0; jb < 2; jb++) {
                uint32_t r0, r1, r2, r3;
                if (!TB) {
                    uint32_t addr = sBs + 2u * ((s * 32 + ks + lr) * 136 + nbase + jb * 16 + lc8);
                    ldsm4t(r0, r1, r2, r3, addr);
                    bf[jb * 2 + 0][0] = r0; bf[jb * 2 + 0][1] = r1;
                    bf[jb * 2 + 1][0] = r2; bf[jb * 2 + 1][1] = r3;
                } else {
                    uint32_t addr = sBs + 2u * ((s * 128 + nbase + jb * 16 + lr) * 40 + ks + lc8);
                    ldsm4(r0, r1, r2, r3, addr);
                    bf[jb * 2 + 0][0] = r0; bf[jb * 2 + 0][1] = r2;
                    bf[jb * 2 + 1][0] = r1; bf[jb * 2 + 1][1] = r3;
                }
            }
            #pragma unroll
            for (int i = 0; i < IT; i++)
                #pragma unroll
                for (int j = 0; j < 4; j++)
                    mma_bf16(acc[i][j], a[i], bf[j]);
        }
        __syncthreads();
    }

    // epilogue
    #pragma unroll
    for (int i = 0; i < IT; i++) {
        int r0 = m0 + mbase + i * 16 + (lane >> 2);
        #pragma unroll
        for (int j = 0; j < 4; j++) {
            int c0 = n0 + nbase + j * 8 + (lane & 3) * 2;
            float b0 = 0.f, b1 = 0.f;
            if (bias) { b0 = bias[c0]; b1 = bias[c0 + 1]; }
            float v00 = acc[i][j][0] + b0, v01 = acc[i][j][1] + b1;
            float v10 = acc[i][j][2] + b0, v11 = acc[i][j][3] + b1;
            if (RELU) {
                v00 = fmaxf(v00, 0.f); v01 = fmaxf(v01, 0.f);
                v10 = fmaxf(v10, 0.f); v11 = fmaxf(v11, 0.f);
            }
            if (RES) {
                v00 += res[(long)r0 * ldc + c0];
                v01 += res[(long)r0 * ldc + c0 + 1];
                v10 += res[(long)(r0 + 8) * ldc + c0];
                v11 += res[(long)(r0 + 8) * ldc + c0 + 1];
            }
            if (OUTBF) {
                *(__nv_bfloat162*)(Cb + cbase + (long)r0 * ldc + c0) =
                    __floats2bfloat162_rn(v00, v01);
                *(__nv_bfloat162*)(Cb + cbase + (long)(r0 + 8) * ldc + c0) =
                    __floats2bfloat162_rn(v10, v11);
            } else {
                *(float2*)(Cf + cbase + (long)r0 * ldc + c0)       = make_float2(v00, v01);
                *(float2*)(Cf + cbase + (long)(r0 + 8) * ldc + c0) = make_float2(v10, v11);
            }
        }
    }
}

// ---------------------------------------------------------------------------
extern "C" void kernel_launch(void* const* d_in, const int* in_sizes, int n_in,
                              void* d_out, int out_size)
{
    const float* data    = (const float*)d_in[0];
    const int*   attn_m  = (const int*)  d_in[1];
    const int*   view    = (const int*)  d_in[2];
    const float* seg_emb = (const float*)d_in[3];
    const float* Wq = (const float*)d_in[4];
    const float* bq = (const float*)d_in[5];
    const float* Wk = (const float*)d_in[6];
    const float* bk = (const float*)d_in[7];
    const float* Wv = (const float*)d_in[8];
    const float* bv = (const float*)d_in[9];
    const float* Wo = (const float*)d_in[10];
    const float* bo = (const float*)d_in[11];
    const float* W1 = (const float*)d_in[12];
    const float* b1 = (const float*)d_in[13];
    const float* W2 = (const float*)d_in[14];
    const float* b2 = (const float*)d_in[15];
    const float* alpha1 = (const float*)d_in[16];
    const float* bias1  = (const float*)d_in[17];
    const float* alpha2 = (const float*)d_in[18];
    const float* bias2  = (const float*)d_in[19];
    const float* alpha_f = (const float*)d_in[20];
    const float* bias_f  = (const float*)d_in[21];
    float* out = (float*)d_out;

    float *x, *s;
    __nv_bfloat16 *x2b, *qb, *kb, *vb, *sb, *ob, *fb;
    __nv_bfloat16 *wq, *wk, *wv, *wo, *w1, *w2;
    cudaGetSymbolAddress((void**)&x,   g_x);
    cudaGetSymbolAddress((void**)&s,   g_s);
    cudaGetSymbolAddress((void**)&x2b, g_x2b);
    cudaGetSymbolAddress((void**)&qb,  g_qb);
    cudaGetSymbolAddress((void**)&kb,  g_kb);
    cudaGetSymbolAddress((void**)&vb,  g_vb);
    cudaGetSymbolAddress((void**)&sb,  g_sb);
    cudaGetSymbolAddress((void**)&ob,  g_ob);
    cudaGetSymbolAddress((void**)&fb,  g_fb);
    cudaGetSymbolAddress((void**)&wq,  g_wq);
    cudaGetSymbolAddress((void**)&wk,  g_wk);
    cudaGetSymbolAddress((void**)&wv,  g_wv);
    cudaGetSymbolAddress((void**)&wo,  g_wo);
    cudaGetSymbolAddress((void**)&w1,  g_w1);
    cudaGetSymbolAddress((void**)&w2,  g_w2);

    cvt_weights<<<(6 * (WSZ / 4)) / 256, 256>>>(Wq, Wk, Wv, Wo, W1, W2);
    embed_kernel<<<(TOK * DMODEL + 255) / 256, 256>>>(data, seg_emb, view, x);

    const long sBH = (long)SS * HD;      // per-batch stride q/k/v/o
    const long sHH = DKH;                // per-head stride
    const long sSB = (long)HEADS * SS * SS;
    const long sSH = (long)SS * SS;

    for (int i = 0; i < LNUM; i++) {
        layernorm_kernel<true><<<TOK, 256>>>(x, alpha1 + i * DMODEL, bias1 + i * DMODEL,
                                             nullptr, x2b);

        dim3 gp(HD / 128, TOK / 128, 1);
        gemm_bf<128,false,false,false,true><<<gp, 256>>>(x2b, wq + (long)i * DMODEL * HD,
            bq + (long)i * HD, nullptr, nullptr, qb, DMODEL, DMODEL, HD, HD, 0,0,0,0,0,0);
        gemm_bf<128,false,false,false,true><<<gp, 256>>>(x2b, wk + (long)i * DMODEL * HD,
            bk + (long)i * HD, nullptr, nullptr, kb, DMODEL, DMODEL, HD, HD, 0,0,0,0,0,0);
        gemm_bf<128,false,false,false,true><<<gp, 256>>>(x2b, wv + (long)i * DMODEL * HD,
            bv + (long)i * HD, nullptr, nullptr, vb, DMODEL, DMODEL, HD, HD, 0,0,0,0,0,0);

        // scores = q @ k^T (batched over 64 heads), fp32 out
        dim3 ga(SS / 128, SS / 128, BB * HEADS);
        gemm_bf<128,true,false,false,false><<<ga, 256>>>(qb, kb, nullptr, nullptr, s, nullptr,
            DKH, HD, HD, SS, sBH, sHH, sBH, sHH, sSB, sSH);

        softmax_kernel<<<(BB * HEADS * SS) / 8, 256>>>(s, sb, attn_m);

        // o = P @ v (batched), bf16 out
        dim3 gv(DKH / 128, SS / 128, BB * HEADS);
        gemm_bf<128,false,false,false,true><<<gv, 256>>>(sb, vb, nullptr, nullptr, nullptr, ob,
            SS, SS, HD, HD, sSB, sSH, sBH, sHH, sBH, sHH);

        // x = x + o @ Wo + bo   (BM=64 for occupancy: 128 CTAs)
        dim3 go(DMODEL / 128, TOK / 64, 1);
        gemm_bf<64,false,false,true,false><<<go, 256>>>(ob, wo + (long)i * HD * DMODEL,
            bo + (long)i * DMODEL, x, x, nullptr, HD, HD, DMODEL, DMODEL, 0,0,0,0,0,0);

        layernorm_kernel<true><<<TOK, 256>>>(x, alpha2 + i * DMODEL, bias2 + i * DMODEL,
                                             nullptr, x2b);

        // ff = relu(x2 @ W1 + b1), bf16 out
        dim3 gf(DFFN / 128, TOK / 128, 1);
        gemm_bf<128,false,true,false,true><<<gf, 256>>>(x2b, w1 + (long)i * DMODEL * DFFN,
            b1 + (long)i * DFFN, nullptr, nullptr, fb, DMODEL, DMODEL, DFFN, DFFN, 0,0,0,0,0,0);

        // x = x + ff @ W2 + b2
        gemm_bf<64,false,false,true,false><<<go, 256>>>(fb, w2 + (long)i * DFFN * DMODEL,
            b2 + (long)i * DMODEL, x, x, nullptr, DFFN, DFFN, DMODEL, DMODEL, 0,0,0,0,0,0);
    }

    layernorm_kernel<false><<<TOK, 256>>>(x, alpha_f, bias_f, out, nullptr);
}

// round 5
// speedup vs baseline: 6.8619x; 1.1364x over previous
#include <cuda_runtime.h>
#include <cuda_bf16.h>
#include <math.h>
#include <stdint.h>

#define LNUM 4
#define DMODEL 512
#define HEADS 8
#define DKH 256
#define DFFN 2048
#define BB 8
#define SS 256
#define HD (HEADS*DKH)          // 2048
#define TOK (BB*SS)             // 2048
#define QKVN (3*HD)             // 6144
#define EPS 1e-6f

// ---------------- scratch (device globals; no allocations) ----------------
__device__ float g_x [TOK*DMODEL];          // fp32 residual stream
__device__ float g_s [BB*HEADS*SS*SS];      // fp32 attention logits

__device__ __nv_bfloat16 g_x2b [TOK*DMODEL];
__device__ __nv_bfloat16 g_qkv [TOK*QKVN];  // packed q|k|v
__device__ __nv_bfloat16 g_sb  [BB*HEADS*SS*SS];
__device__ __nv_bfloat16 g_ob  [TOK*HD];
__device__ __nv_bfloat16 g_fb  [TOK*DFFN];
// bf16 weights
#define WSZ 4194304                          // 4*512*2048
__device__ __nv_bfloat16 g_wqkv[LNUM*DMODEL*QKVN];   // packed per-layer [512][6144]
__device__ float         g_bqkv[LNUM*QKVN];
__device__ __nv_bfloat16 g_wo[WSZ];
__device__ __nv_bfloat16 g_w1[WSZ];
__device__ __nv_bfloat16 g_w2[WSZ];

// ---------------- PTX helpers ---------------------------------------------
__device__ __forceinline__ void cpa16(uint32_t dst, const void* src) {
    asm volatile("cp.async.cg.shared.global [%0], [%1], 16;" :: "r"(dst), "l"(src) : "memory");
}
__device__ __forceinline__ void cp_commit() {
    asm volatile("cp.async.commit_group;" ::: "memory");
}
template<int N>
__device__ __forceinline__ void cp_wait() {
    asm volatile("cp.async.wait_group %0;" :: "n"(N) : "memory");
}
__device__ __forceinline__ void ldsm4(uint32_t& r0, uint32_t& r1, uint32_t& r2, uint32_t& r3, uint32_t a) {
    asm volatile("ldmatrix.sync.aligned.m8n8.x4.shared.b16 {%0,%1,%2,%3}, [%4];"
                 : "=r"(r0), "=r"(r1), "=r"(r2), "=r"(r3) : "r"(a));
}
__device__ __forceinline__ void ldsm4t(uint32_t& r0, uint32_t& r1, uint32_t& r2, uint32_t& r3, uint32_t a) {
    asm volatile("ldmatrix.sync.aligned.m8n8.x4.trans.shared.b16 {%0,%1,%2,%3}, [%4];"
                 : "=r"(r0), "=r"(r1), "=r"(r2), "=r"(r3) : "r"(a));
}
__device__ __forceinline__ void mma_bf16(float* d, const uint32_t* a, const uint32_t* b) {
    asm volatile("mma.sync.aligned.m16n8k16.row.col.f32.bf16.bf16.f32 "
                 "{%0,%1,%2,%3}, {%4,%5,%6,%7}, {%8,%9}, {%0,%1,%2,%3};"
                 : "+f"(d[0]), "+f"(d[1]), "+f"(d[2]), "+f"(d[3])
                 : "r"(a[0]), "r"(a[1]), "r"(a[2]), "r"(a[3]), "r"(b[0]), "r"(b[1]));
}

// ---------------- weight fp32 -> bf16 (once per launch) -------------------
// qkv packed: g_wqkv[l][row][which*2048 + col]
__global__ void cvt_weights(const float* __restrict__ wq, const float* __restrict__ wk,
                            const float* __restrict__ wv, const float* __restrict__ wo,
                            const float* __restrict__ w1, const float* __restrict__ w2)
{
    long i4 = (long)blockIdx.x * blockDim.x + threadIdx.x;   // 6 * 2^20 threads
    int which = (int)(i4 >> 20);
    long off = (i4 & ((1L << 20) - 1)) << 2;                 // elem offset, mult of 4
    const float* s;
    __nv_bfloat16* d;
    long doff = off;
    if (which < 3) {
        s = (which == 0) ? wq : (which == 1) ? wk : wv;
        long l   = off / ((long)DMODEL * HD);
        long win = off - l * (long)DMODEL * HD;
        long row = win / HD;
        long col = win - row * HD;
        d = g_wqkv;
        doff = l * (long)DMODEL * QKVN + row * QKVN + which * HD + col;
    } else {
        s = (which == 3) ? wo : (which == 4) ? w1 : w2;
        d = (which == 3) ? g_wo : (which == 4) ? g_w1 : g_w2;
    }
    float4 v = *(const float4*)(s + off);
    *(__nv_bfloat162*)(d + doff)     = __floats2bfloat162_rn(v.x, v.y);
    *(__nv_bfloat162*)(d + doff + 2) = __floats2bfloat162_rn(v.z, v.w);
}

__global__ void cvt_bias(const float* __restrict__ bq, const float* __restrict__ bk,
                         const float* __restrict__ bv)
{
    int idx = blockIdx.x * blockDim.x + threadIdx.x;         // LNUM*QKVN
    if (idx >= LNUM * QKVN) return;
    int l = idx / QKVN;
    int c = idx - l * QKVN;
    int which = c >> 11;                                     // /2048
    int col = c & (HD - 1);
    const float* s = (which == 0) ? bq : (which == 1) ? bk : bv;
    g_bqkv[idx] = s[l * HD + col];
}

// ---------------- embed ----------------------------------------------------
__global__ void embed_kernel(const float* __restrict__ data,
                             const float* __restrict__ seg_emb,
                             const int* __restrict__ view,
                             float* __restrict__ x)
{
    int idx = blockIdx.x * blockDim.x + threadIdx.x;
    if (idx >= TOK * DMODEL) return;
    int c = idx & (DMODEL - 1);
    int s = (idx >> 9) & (SS - 1);
    float inv = exp2f(-(float)c * (1.0f / 32.0f));
    float arg = (float)s * inv;
    float pe  = (c & 1) ? cosf(arg) : sinf(arg);
    int seg_off = view[0] * SS * DMODEL + c;
    x[idx] = data[idx] * sqrtf((float)DMODEL) + pe + seg_emb[seg_off];
}

// ---------------- layernorm: fp32 in, bf16 (or fp32) out ------------------
template<bool OB>
__global__ void layernorm_kernel(const float* __restrict__ x,
                                 const float* __restrict__ alpha,
                                 const float* __restrict__ beta,
                                 float* __restrict__ outf,
                                 __nv_bfloat16* __restrict__ outb)
{
    int row = blockIdx.x;
    int tid = threadIdx.x;
    const float* p = x + (long)row * DMODEL;
    float v0 = p[tid];
    float v1 = p[tid + 256];
    float s  = v0 + v1;
    float sq = v0 * v0 + v1 * v1;

    #pragma unroll
    for (int off = 16; off > 0; off >>= 1) {
        s  += __shfl_xor_sync(0xffffffff, s,  off);
        sq += __shfl_xor_sync(0xffffffff, sq, off);
    }
    __shared__ float shs[8], shq[8];
    int wid = tid >> 5, lane = tid & 31;
    if (lane == 0) { shs[wid] = s; shq[wid] = sq; }
    __syncthreads();
    float S = 0.f, SQ = 0.f;
    #pragma unroll
    for (int w = 0; w < 8; w++) { S += shs[w]; SQ += shq[w]; }

    float mean = S * (1.0f / DMODEL);
    float var  = (SQ - (float)DMODEL * mean * mean) * (1.0f / (DMODEL - 1));
    var = fmaxf(var, 0.f);
    float rinv = 1.0f / (sqrtf(var) + EPS);

    float o0 = alpha[tid]       * (v0 - mean) * rinv + beta[tid];
    float o1 = alpha[tid + 256] * (v1 - mean) * rinv + beta[tid + 256];
    if (OB) {
        outb[(long)row * DMODEL + tid]       = __float2bfloat16(o0);
        outb[(long)row * DMODEL + tid + 256] = __float2bfloat16(o1);
    } else {
        outf[(long)row * DMODEL + tid]       = o0;
        outf[(long)row * DMODEL + tid + 256] = o1;
    }
}

// ---------------- masked softmax: fp32 logits in, bf16 probs out ----------
__global__ void softmax_kernel(const float* __restrict__ sc,
                               __nv_bfloat16* __restrict__ sb,
                               const int* __restrict__ attn_m)
{
    int gwarp = (blockIdx.x * blockDim.x + threadIdx.x) >> 5;
    int lane  = threadIdx.x & 31;
    int b = gwarp >> 11;
    const float* p = sc + (long)gwarp * SS;
    __nv_bfloat16* q = sb + (long)gwarp * SS;
    const int* m = attn_m + b * SS;

    float v[8];
    float mx = -1e30f;
    #pragma unroll
    for (int j = 0; j < 8; j++) {
        int t = lane + (j << 5);
        float val = m[t] ? -1e9f : p[t] * 0.0625f;
        v[j] = val;
        mx = fmaxf(mx, val);
    }
    #pragma unroll
    for (int off = 16; off > 0; off >>= 1)
        mx = fmaxf(mx, __shfl_xor_sync(0xffffffff, mx, off));
    float sum = 0.f;
    #pragma unroll
    for (int j = 0; j < 8; j++) { v[j] = expf(v[j] - mx); sum += v[j]; }
    #pragma unroll
    for (int off = 16; off > 0; off >>= 1)
        sum += __shfl_xor_sync(0xffffffff, sum, off);
    float r = 1.0f / sum;
    #pragma unroll
    for (int j = 0; j < 8; j++) q[lane + (j << 5)] = __float2bfloat16(v[j] * r);
}

// ---------------- bf16 tensor-core GEMM, 3-stage cp.async pipeline --------
// C[M,N]=A[M,K]@B(K,N) (+bias)(+relu)(+res). TB: B stored [N,K].
// CTA: BM x 128 x 32. 8 warps (2 M x 4 N). mma m16n8k16 bf16, fp32 acc.
#define NSTAGE 3
template<int BM, bool TB>
struct SmemCfg {
    static constexpr int BROWS = TB ? 128 : 32;
    static constexpr int BCOLS = TB ? 40 : 136;
    static constexpr int A_ELEMS = NSTAGE * BM * 40;
    static constexpr int B_ELEMS = NSTAGE * BROWS * BCOLS;
    static constexpr int BYTES = (A_ELEMS + B_ELEMS) * 2;
};

template<int BM, bool TB, bool RELU, bool RES, bool OUTBF>
__global__ void __launch_bounds__(256)
gemm_bf(const __nv_bfloat16* __restrict__ A, const __nv_bfloat16* __restrict__ B,
        const float* __restrict__ bias, const float* __restrict__ res,
        float* __restrict__ Cf, __nv_bfloat16* __restrict__ Cb,
        int K, int lda, int ldb, int ldc,
        long sAb, long sAh, long sBb, long sBh, long sCb, long sCh)
{
    constexpr int IT = BM / 32;
    constexpr int BROWS = SmemCfg<BM,TB>::BROWS;
    constexpr int BCOLS = SmemCfg<BM,TB>::BCOLS;

    extern __shared__ __align__(16) char smem_raw[];
    __nv_bfloat16* As = (__nv_bfloat16*)smem_raw;                 // [NSTAGE][BM][40]
    __nv_bfloat16* Bs = As + SmemCfg<BM,TB>::A_ELEMS;             // [NSTAGE][BROWS][BCOLS]

    int z = blockIdx.z;
    int bb = z >> 3, hh = z & 7;
    A += bb * sAb + hh * sAh;
    B += bb * sBb + hh * sBh;
    if (RES) res += bb * sCb + hh * sCh;
    long cbase = bb * sCb + hh * sCh;

    const int m0 = blockIdx.y * BM, n0 = blockIdx.x << 7;
    const int tid  = threadIdx.x;
    const int wid  = tid >> 5;
    const int lane = tid & 31;
    const int mbase = (wid >> 2) * (BM / 2);
    const int nbase = (wid & 3) * 32;
    const int lr  = ((lane >> 3) & 1) * 8 + (lane & 7);
    const int lc8 = (lane >> 4) * 8;

    uint32_t sAs = (uint32_t)__cvta_generic_to_shared(As);
    uint32_t sBs = (uint32_t)__cvta_generic_to_shared(Bs);

    float acc[IT][4][4];
    #pragma unroll
    for (int i = 0; i < IT; i++)
        #pragma unroll
        for (int j = 0; j < 4; j++)
            #pragma unroll
            for (int r = 0; r < 4; r++) acc[i][j][r] = 0.f;

    auto stage = [&](int s, int kb) {
        #pragma unroll
        for (int t = 0; t < BM / 64; t++) {
            int idx = tid + t * 256;
            int row = idx >> 2, ck = idx & 3;
            uint32_t d = sAs + 2u * ((s * BM + row) * 40 + ck * 8);
            cpa16(d, A + (long)(m0 + row) * lda + kb + ck * 8);
        }
        if (!TB) {
            #pragma unroll
            for (int t = 0; t < 2; t++) {
                int idx = tid + t * 256;
                int row = idx >> 4, ck = idx & 15;
                uint32_t d = sBs + 2u * ((s * 32 + row) * 136 + ck * 8);
                cpa16(d, B + (long)(kb + row) * ldb + n0 + ck * 8);
            }
        } else {
            #pragma unroll
            for (int t = 0; t < 2; t++) {
                int idx = tid + t * 256;
                int row = idx >> 2, ck = idx & 3;
                uint32_t d = sBs + 2u * ((s * 128 + row) * 40 + ck * 8);
                cpa16(d, B + (long)(n0 + row) * ldb + kb + ck * 8);
            }
        }
    };

    const int NIT = K >> 5;
    stage(0, 0);
    cp_commit();
    if (NIT > 1) stage(1, 32);
    cp_commit();

    int s = 0;
    for (int it = 0; it < NIT; it++) {
        cp_wait<1>();
        __syncthreads();

        #pragma unroll
        for (int ks = 0; ks < 32; ks += 16) {
            uint32_t a[IT][4], bf[4][2];
            #pragma unroll
            for (int i = 0; i < IT; i++) {
                uint32_t addr = sAs + 2u * ((s * BM + mbase + i * 16 + lr) * 40 + ks + lc8);
                ldsm4(a[i][0], a[i][1], a[i][2], a[i][3], addr);
            }
            #pragma unroll
            for (int jb = 0; jb < 2; jb++) {
                uint32_t r0, r1, r2, r3;
                if (!TB) {
                    uint32_t addr = sBs + 2u * ((s * 32 + ks + lr) * 136 + nbase + jb * 16 + lc8);
                    ldsm4t(r0, r1, r2, r3, addr);
                    bf[jb * 2 + 0][0] = r0; bf[jb * 2 + 0][1] = r1;
                    bf[jb * 2 + 1][0] = r2; bf[jb * 2 + 1][1] = r3;
                } else {
                    uint32_t addr = sBs + 2u * ((s * 128 + nbase + jb * 16 + lr) * 40 + ks + lc8);
                    ldsm4(r0, r1, r2, r3, addr);
                    bf[jb * 2 + 0][0] = r0; bf[jb * 2 + 0][1] = r2;
                    bf[jb * 2 + 1][0] = r1; bf[jb * 2 + 1][1] = r3;
                }
            }
            #pragma unroll
            for (int i = 0; i < IT; i++)
                #pragma unroll
                for (int j = 0; j < 4; j++)
                    mma_bf16(acc[i][j], a[i], bf[j]);
        }

        // next-next stage: buffer (it+2)%3 was last read at iteration it-1,
        // and all warps passed the sync at top of this iteration -> safe.
        __syncthreads();
        if (it + 2 < NIT) {
            int sn = s + 2; if (sn >= NSTAGE) sn -= NSTAGE;
            stage(sn, (it + 2) << 5);
        }
        cp_commit();   // empty group near tail keeps wait<1> accounting exact

        if (++s == NSTAGE) s = 0;
    }

    // epilogue
    #pragma unroll
    for (int i = 0; i < IT; i++) {
        int r0 = m0 + mbase + i * 16 + (lane >> 2);
        #pragma unroll
        for (int j = 0; j < 4; j++) {
            int c0 = n0 + nbase + j * 8 + (lane & 3) * 2;
            float b0 = 0.f, b1 = 0.f;
            if (bias) { b0 = bias[c0]; b1 = bias[c0 + 1]; }
            float v00 = acc[i][j][0] + b0, v01 = acc[i][j][1] + b1;
            float v10 = acc[i][j][2] + b0, v11 = acc[i][j][3] + b1;
            if (RELU) {
                v00 = fmaxf(v00, 0.f); v01 = fmaxf(v01, 0.f);
                v10 = fmaxf(v10, 0.f); v11 = fmaxf(v11, 0.f);
            }
            if (RES) {
                v00 += res[(long)r0 * ldc + c0];
                v01 += res[(long)r0 * ldc + c0 + 1];
                v10 += res[(long)(r0 + 8) * ldc + c0];
                v11 += res[(long)(r0 + 8) * ldc + c0 + 1];
            }
            if (OUTBF) {
                *(__nv_bfloat162*)(Cb + cbase + (long)r0 * ldc + c0) =
                    __floats2bfloat162_rn(v00, v01);
                *(__nv_bfloat162*)(Cb + cbase + (long)(r0 + 8) * ldc + c0) =
                    __floats2bfloat162_rn(v10, v11);
            } else {
                *(float2*)(Cf + cbase + (long)r0 * ldc + c0)       = make_float2(v00, v01);
                *(float2*)(Cf + cbase + (long)(r0 + 8) * ldc + c0) = make_float2(v10, v11);
            }
        }
    }
}

// ---------------------------------------------------------------------------
extern "C" void kernel_launch(void* const* d_in, const int* in_sizes, int n_in,
                              void* d_out, int out_size)
{
    const float* data    = (const float*)d_in[0];
    const int*   attn_m  = (const int*)  d_in[1];
    const int*   view    = (const int*)  d_in[2];
    const float* seg_emb = (const float*)d_in[3];
    const float* Wq = (const float*)d_in[4];
    const float* bq = (const float*)d_in[5];
    const float* Wk = (const float*)d_in[6];
    const float* bk = (const float*)d_in[7];
    const float* Wv = (const float*)d_in[8];
    const float* bv = (const float*)d_in[9];
    const float* Wo = (const float*)d_in[10];
    const float* bo = (const float*)d_in[11];
    const float* W1 = (const float*)d_in[12];
    const float* b1 = (const float*)d_in[13];
    const float* W2 = (const float*)d_in[14];
    const float* b2 = (const float*)d_in[15];
    const float* alpha1 = (const float*)d_in[16];
    const float* bias1  = (const float*)d_in[17];
    const float* alpha2 = (const float*)d_in[18];
    const float* bias2  = (const float*)d_in[19];
    const float* alpha_f = (const float*)d_in[20];
    const float* bias_f  = (const float*)d_in[21];
    float* out = (float*)d_out;

    float *x, *s;
    __nv_bfloat16 *x2b, *qkv, *sb, *ob, *fb;
    __nv_bfloat16 *wqkv, *wo, *w1, *w2;
    float *bqkv;
    cudaGetSymbolAddress((void**)&x,    g_x);
    cudaGetSymbolAddress((void**)&s,    g_s);
    cudaGetSymbolAddress((void**)&x2b,  g_x2b);
    cudaGetSymbolAddress((void**)&qkv,  g_qkv);
    cudaGetSymbolAddress((void**)&sb,   g_sb);
    cudaGetSymbolAddress((void**)&ob,   g_ob);
    cudaGetSymbolAddress((void**)&fb,   g_fb);
    cudaGetSymbolAddress((void**)&wqkv, g_wqkv);
    cudaGetSymbolAddress((void**)&bqkv, g_bqkv);
    cudaGetSymbolAddress((void**)&wo,   g_wo);
    cudaGetSymbolAddress((void**)&w1,   g_w1);
    cudaGetSymbolAddress((void**)&w2,   g_w2);

    // opt-in > 48KB dynamic smem (host-side attribute; capture-safe, idempotent)
    constexpr int SM_NN128 = SmemCfg<128,false>::BYTES;   // 56832
    constexpr int SM_TB128 = SmemCfg<128,true >::BYTES;   // 61440
    constexpr int SM_NN64  = SmemCfg<64, false>::BYTES;   // 41472
    cudaFuncSetAttribute(gemm_bf<128,false,false,false,true>,
        cudaFuncAttributeMaxDynamicSharedMemorySize, SM_NN128);
    cudaFuncSetAttribute(gemm_bf<128,true,false,false,false>,
        cudaFuncAttributeMaxDynamicSharedMemorySize, SM_TB128);
    cudaFuncSetAttribute(gemm_bf<128,false,true,false,true>,
        cudaFuncAttributeMaxDynamicSharedMemorySize, SM_NN128);
    cudaFuncSetAttribute(gemm_bf<64,false,false,true,false>,
        cudaFuncAttributeMaxDynamicSharedMemorySize, SM_NN64);

    cvt_weights<<<(6 * (WSZ / 4)) / 256, 256>>>(Wq, Wk, Wv, Wo, W1, W2);
    cvt_bias<<<(LNUM * QKVN + 255) / 256, 256>>>(bq, bk, bv);
    embed_kernel<<<(TOK * DMODEL + 255) / 256, 256>>>(data, seg_emb, view, x);

    // attention strides on the packed qkv buffer [TOK][6144]
    const long sQb = (long)SS * QKVN;    // per-batch
    const long sQh = DKH;                // per-head
    const long sSB = (long)HEADS * SS * SS;
    const long sSH = (long)SS * SS;
    const long sOb = (long)SS * HD;
    const long sOh = DKH;

    for (int i = 0; i < LNUM; i++) {
        layernorm_kernel<true><<<TOK, 256>>>(x, alpha1 + i * DMODEL, bias1 + i * DMODEL,
                                             nullptr, x2b);

        // fused QKV: [2048,512] @ [512,6144]
        dim3 gp(QKVN / 128, TOK / 128, 1);
        gemm_bf<128,false,false,false,true><<<gp, 256, SM_NN128>>>(
            x2b, wqkv + (long)i * DMODEL * QKVN, bqkv + (long)i * QKVN,
            nullptr, nullptr, qkv, DMODEL, DMODEL, QKVN, QKVN, 0,0,0,0,0,0);

        // scores = q @ k^T (batched over 64 heads), fp32 out
        dim3 ga(SS / 128, SS / 128, BB * HEADS);
        gemm_bf<128,true,false,false,false><<<ga, 256, SM_TB128>>>(
            qkv, qkv + HD, nullptr, nullptr, s, nullptr,
            DKH, QKVN, QKVN, SS, sQb, sQh, sQb, sQh, sSB, sSH);

        softmax_kernel<<<(BB * HEADS * SS) / 8, 256>>>(s, sb, attn_m);

        // o = P @ v (batched), bf16 out
        dim3 gv(DKH / 128, SS / 128, BB * HEADS);
        gemm_bf<128,false,false,false,true><<<gv, 256, SM_NN128>>>(
            sb, qkv + 2 * HD, nullptr, nullptr, nullptr, ob,
            SS, SS, QKVN, HD, sSB, sSH, sQb, sQh, sOb, sOh);

        // x = x + o @ Wo + bo
        dim3 go(DMODEL / 128, TOK / 64, 1);
        gemm_bf<64,false,false,true,false><<<go, 256, SM_NN64>>>(
            ob, wo + (long)i * HD * DMODEL, bo + (long)i * DMODEL,
            x, x, nullptr, HD, HD, DMODEL, DMODEL, 0,0,0,0,0,0);

        layernorm_kernel<true><<<TOK, 256>>>(x, alpha2 + i * DMODEL, bias2 + i * DMODEL,
                                             nullptr, x2b);

        // ff = relu(x2 @ W1 + b1)
        dim3 gf(DFFN / 128, TOK / 128, 1);
        gemm_bf<128,false,true,false,true><<<gf, 256, SM_NN128>>>(
            x2b, w1 + (long)i * DMODEL * DFFN, b1 + (long)i * DFFN,
            nullptr, nullptr, fb, DMODEL, DMODEL, DFFN, DFFN, 0,0,0,0,0,0);

        // x = x + ff @ W2 + b2
        gemm_bf<64,false,false,true,false><<<go, 256, SM_NN64>>>(
            fb, w2 + (long)i * DFFN * DMODEL, b2 + (long)i * DMODEL,
            x, x, nullptr, DFFN, DFFN, DMODEL, DMODEL, 0,0,0,0,0,0);
    }

    layernorm_kernel<false><<<TOK, 256>>>(x, alpha_f, bias_f, out, nullptr);
}

// round 6
// speedup vs baseline: 6.9995x; 1.0201x over previous
#include <cuda_runtime.h>
#include <cuda_bf16.h>
#include <math.h>
#include <stdint.h>

#define LNUM 4
#define DMODEL 512
#define HEADS 8
#define DKH 256
#define DFFN 2048
#define BB 8
#define SS 256
#define HD (HEADS*DKH)          // 2048
#define TOK (BB*SS)             // 2048
#define QKVN (3*HD)             // 6144
#define EPS 1e-6f

// ---------------- scratch (device globals; no allocations) ----------------
__device__ float g_x [TOK*DMODEL];          // fp32 residual stream

__device__ __nv_bfloat16 g_x2b [TOK*DMODEL];
__device__ __nv_bfloat16 g_qkv [TOK*QKVN];  // packed q|k|v
__device__ __nv_bfloat16 g_sb  [BB*HEADS*SS*SS];   // bf16 probs
__device__ __nv_bfloat16 g_ob  [TOK*HD];
__device__ __nv_bfloat16 g_fb  [TOK*DFFN];
// bf16 weights
#define WSZ 4194304                          // 4*512*2048
__device__ __nv_bfloat16 g_wqkv[LNUM*DMODEL*QKVN];   // packed per-layer [512][6144]
__device__ float         g_bqkv[LNUM*QKVN];
__device__ __nv_bfloat16 g_wo[WSZ];
__device__ __nv_bfloat16 g_w1[WSZ];
__device__ __nv_bfloat16 g_w2[WSZ];

// ---------------- PTX helpers ---------------------------------------------
__device__ __forceinline__ void cpa16(uint32_t dst, const void* src) {
    asm volatile("cp.async.cg.shared.global [%0], [%1], 16;" :: "r"(dst), "l"(src) : "memory");
}
__device__ __forceinline__ void cp_commit() {
    asm volatile("cp.async.commit_group;" ::: "memory");
}
template<int N>
__device__ __forceinline__ void cp_wait() {
    asm volatile("cp.async.wait_group %0;" :: "n"(N) : "memory");
}
__device__ __forceinline__ void ldsm4(uint32_t& r0, uint32_t& r1, uint32_t& r2, uint32_t& r3, uint32_t a) {
    asm volatile("ldmatrix.sync.aligned.m8n8.x4.shared.b16 {%0,%1,%2,%3}, [%4];"
                 : "=r"(r0), "=r"(r1), "=r"(r2), "=r"(r3) : "r"(a));
}
__device__ __forceinline__ void ldsm4t(uint32_t& r0, uint32_t& r1, uint32_t& r2, uint32_t& r3, uint32_t a) {
    asm volatile("ldmatrix.sync.aligned.m8n8.x4.trans.shared.b16 {%0,%1,%2,%3}, [%4];"
                 : "=r"(r0), "=r"(r1), "=r"(r2), "=r"(r3) : "r"(a));
}
__device__ __forceinline__ void mma_bf16(float* d, const uint32_t* a, const uint32_t* b) {
    asm volatile("mma.sync.aligned.m16n8k16.row.col.f32.bf16.bf16.f32 "
                 "{%0,%1,%2,%3}, {%4,%5,%6,%7}, {%8,%9}, {%0,%1,%2,%3};"
                 : "+f"(d[0]), "+f"(d[1]), "+f"(d[2]), "+f"(d[3])
                 : "r"(a[0]), "r"(a[1]), "r"(a[2]), "r"(a[3]), "r"(b[0]), "r"(b[1]));
}

// ---------------- weight fp32 -> bf16 (once per launch) -------------------
__global__ void cvt_weights(const float* __restrict__ wq, const float* __restrict__ wk,
                            const float* __restrict__ wv, const float* __restrict__ wo,
                            const float* __restrict__ w1, const float* __restrict__ w2)
{
    long i4 = (long)blockIdx.x * blockDim.x + threadIdx.x;
    int which = (int)(i4 >> 20);
    long off = (i4 & ((1L << 20) - 1)) << 2;
    const float* s;
    __nv_bfloat16* d;
    long doff = off;
    if (which < 3) {
        s = (which == 0) ? wq : (which == 1) ? wk : wv;
        long l   = off / ((long)DMODEL * HD);
        long win = off - l * (long)DMODEL * HD;
        long row = win / HD;
        long col = win - row * HD;
        d = g_wqkv;
        doff = l * (long)DMODEL * QKVN + row * QKVN + which * HD + col;
    } else {
        s = (which == 3) ? wo : (which == 4) ? w1 : w2;
        d = (which == 3) ? g_wo : (which == 4) ? g_w1 : g_w2;
    }
    float4 v = *(const float4*)(s + off);
    *(__nv_bfloat162*)(d + doff)     = __floats2bfloat162_rn(v.x, v.y);
    *(__nv_bfloat162*)(d + doff + 2) = __floats2bfloat162_rn(v.z, v.w);
}

__global__ void cvt_bias(const float* __restrict__ bq, const float* __restrict__ bk,
                         const float* __restrict__ bv)
{
    int idx = blockIdx.x * blockDim.x + threadIdx.x;
    if (idx >= LNUM * QKVN) return;
    int l = idx / QKVN;
    int c = idx - l * QKVN;
    int which = c >> 11;
    int col = c & (HD - 1);
    const float* s = (which == 0) ? bq : (which == 1) ? bk : bv;
    g_bqkv[idx] = s[l * HD + col];
}

// ---------------- embed ----------------------------------------------------
__global__ void embed_kernel(const float* __restrict__ data,
                             const float* __restrict__ seg_emb,
                             const int* __restrict__ view,
                             float* __restrict__ x)
{
    int idx = blockIdx.x * blockDim.x + threadIdx.x;
    if (idx >= TOK * DMODEL) return;
    int c = idx & (DMODEL - 1);
    int s = (idx >> 9) & (SS - 1);
    float inv = exp2f(-(float)c * (1.0f / 32.0f));
    float arg = (float)s * inv;
    float pe  = (c & 1) ? cosf(arg) : sinf(arg);
    int seg_off = view[0] * SS * DMODEL + c;
    x[idx] = data[idx] * sqrtf((float)DMODEL) + pe + seg_emb[seg_off];
}

// ---------------- layernorm: fp32 in, bf16 (or fp32) out ------------------
template<bool OB>
__global__ void layernorm_kernel(const float* __restrict__ x,
                                 const float* __restrict__ alpha,
                                 const float* __restrict__ beta,
                                 float* __restrict__ outf,
                                 __nv_bfloat16* __restrict__ outb)
{
    int row = blockIdx.x;
    int tid = threadIdx.x;
    const float* p = x + (long)row * DMODEL;
    float v0 = p[tid];
    float v1 = p[tid + 256];
    float s  = v0 + v1;
    float sq = v0 * v0 + v1 * v1;

    #pragma unroll
    for (int off = 16; off > 0; off >>= 1) {
        s  += __shfl_xor_sync(0xffffffff, s,  off);
        sq += __shfl_xor_sync(0xffffffff, sq, off);
    }
    __shared__ float shs[8], shq[8];
    int wid = tid >> 5, lane = tid & 31;
    if (lane == 0) { shs[wid] = s; shq[wid] = sq; }
    __syncthreads();
    float S = 0.f, SQ = 0.f;
    #pragma unroll
    for (int w = 0; w < 8; w++) { S += shs[w]; SQ += shq[w]; }

    float mean = S * (1.0f / DMODEL);
    float var  = (SQ - (float)DMODEL * mean * mean) * (1.0f / (DMODEL - 1));
    var = fmaxf(var, 0.f);
    float rinv = 1.0f / (sqrtf(var) + EPS);

    float o0 = alpha[tid]       * (v0 - mean) * rinv + beta[tid];
    float o1 = alpha[tid + 256] * (v1 - mean) * rinv + beta[tid + 256];
    if (OB) {
        outb[(long)row * DMODEL + tid]       = __float2bfloat16(o0);
        outb[(long)row * DMODEL + tid + 256] = __float2bfloat16(o1);
    } else {
        outf[(long)row * DMODEL + tid]       = o0;
        outf[(long)row * DMODEL + tid + 256] = o1;
    }
}

// ---------------- fused scores GEMM + mask + softmax ----------------------
// CTA: 128 q-rows x 256 keys (full row), one (b,h) per blockIdx.y.
// S = q @ k^T, masked softmax in-CTA, bf16 probs out. 8 warps (2M x 4N), 64x64/warp.
#define ATT_NST 3
#define ATT_MAIN_ELEMS (ATT_NST*128*40 + ATT_NST*256*40)        // bf16 elems
#define ATT_SMEM_BYTES (128*264*4)                               // epilogue S (bigger)

__global__ void __launch_bounds__(256)
attn_scores_softmax(const __nv_bfloat16* __restrict__ qkv,
                    const int* __restrict__ attn_m,
                    __nv_bfloat16* __restrict__ sb)
{
    extern __shared__ __align__(16) char smem_raw[];
    __nv_bfloat16* As = (__nv_bfloat16*)smem_raw;        // [3][128][40]
    __nv_bfloat16* Bs = As + ATT_NST * 128 * 40;         // [3][256][40]
    float* Ssm = (float*)smem_raw;                        // [128][264] (reuse)
    __shared__ int msk[SS];

    const int z = blockIdx.y;            // b*8+h
    const int b = z >> 3, h = z & 7;
    const int m0 = blockIdx.x << 7;      // q-tile
    const long sQb = (long)SS * QKVN;
    const __nv_bfloat16* A = qkv + b * sQb + (long)h * DKH + (long)m0 * QKVN;
    const __nv_bfloat16* B = qkv + HD + b * sQb + (long)h * DKH;

    const int tid  = threadIdx.x;
    const int wid  = tid >> 5;
    const int lane = tid & 31;
    const int mbase = (wid >> 2) * 64;   // 0/64
    const int nbase = (wid & 3) * 64;    // 0..192
    const int lr  = ((lane >> 3) & 1) * 8 + (lane & 7);
    const int lc8 = (lane >> 4) * 8;
    const int lg = lane >> 2, lt = lane & 3;

    if (tid < SS) msk[tid] = attn_m[b * SS + tid];

    uint32_t sAs = (uint32_t)__cvta_generic_to_shared(As);
    uint32_t sBs = (uint32_t)__cvta_generic_to_shared(Bs);

    float acc[4][8][4];
    #pragma unroll
    for (int i = 0; i < 4; i++)
        #pragma unroll
        for (int j = 0; j < 8; j++)
            #pragma unroll
            for (int r = 0; r < 4; r++) acc[i][j][r] = 0.f;

    auto stage = [&](int s, int kb) {
        #pragma unroll
        for (int t = 0; t < 2; t++) {                 // A: 128 rows x 32 k
            int idx = tid + t * 256;
            int row = idx >> 2, ck = idx & 3;
            uint32_t d = sAs + 2u * ((s * 128 + row) * 40 + ck * 8);
            cpa16(d, A + (long)row * QKVN + kb + ck * 8);
        }
        #pragma unroll
        for (int t = 0; t < 4; t++) {                 // B: 256 n-rows x 32 k
            int idx = tid + t * 256;
            int row = idx >> 2, ck = idx & 3;
            uint32_t d = sBs + 2u * ((s * 256 + row) * 40 + ck * 8);
            cpa16(d, B + (long)row * QKVN + kb + ck * 8);
        }
    };

    const int NIT = DKH / 32;     // 8
    stage(0, 0);  cp_commit();
    stage(1, 32); cp_commit();

    int s = 0;
    for (int it = 0; it < NIT; it++) {
        cp_wait<1>();
        __syncthreads();

        #pragma unroll
        for (int ks = 0; ks < 32; ks += 16) {
            uint32_t a[4][4], bf[8][2];
            #pragma unroll
            for (int i = 0; i < 4; i++) {
                uint32_t addr = sAs + 2u * ((s * 128 + mbase + i * 16 + lr) * 40 + ks + lc8);
                ldsm4(a[i][0], a[i][1], a[i][2], a[i][3], addr);
            }
            #pragma unroll
            for (int jb = 0; jb < 4; jb++) {
                uint32_t r0, r1, r2, r3;
                uint32_t addr = sBs + 2u * ((s * 256 + nbase + jb * 16 + lr) * 40 + ks + lc8);
                ldsm4(r0, r1, r2, r3, addr);
                bf[jb * 2 + 0][0] = r0; bf[jb * 2 + 0][1] = r2;
                bf[jb * 2 + 1][0] = r1; bf[jb * 2 + 1][1] = r3;
            }
            #pragma unroll
            for (int i = 0; i < 4; i++)
                #pragma unroll
                for (int j = 0; j < 8; j++)
                    mma_bf16(acc[i][j], a[i], bf[j]);
        }

        __syncthreads();
        if (it + 2 < NIT) {
            int sn = s + 2; if (sn >= ATT_NST) sn -= ATT_NST;
            stage(sn, (it + 2) << 5);
        }
        cp_commit();
        if (++s == ATT_NST) s = 0;
    }

    // ---- epilogue: S -> smem, per-row masked softmax, bf16 out ----
    cp_wait<0>();
    __syncthreads();            // all pipeline smem reads/writes done; safe to reuse

    #pragma unroll
    for (int i = 0; i < 4; i++) {
        int r0 = mbase + i * 16 + lg;
        #pragma unroll
        for (int j = 0; j < 8; j++) {
            int c0 = nbase + j * 8 + lt * 2;
            Ssm[r0 * 264 + c0]           = acc[i][j][0];
            Ssm[r0 * 264 + c0 + 1]       = acc[i][j][1];
            Ssm[(r0 + 8) * 264 + c0]     = acc[i][j][2];
            Ssm[(r0 + 8) * 264 + c0 + 1] = acc[i][j][3];
        }
    }
    __syncthreads();

    __nv_bfloat16* prow_base = sb + ((long)z * SS + m0) * SS;
    #pragma unroll
    for (int r = 0; r < 16; r++) {
        int row = wid * 16 + r;
        const float* srow = Ssm + row * 264;
        float v[8];
        float mx = -1e30f;
        #pragma unroll
        for (int j = 0; j < 8; j++) {
            int col = lane + (j << 5);
            float val = msk[col] ? -1e9f : srow[col] * 0.0625f;
            v[j] = val;
            mx = fmaxf(mx, val);
        }
        #pragma unroll
        for (int off = 16; off > 0; off >>= 1)
            mx = fmaxf(mx, __shfl_xor_sync(0xffffffff, mx, off));
        float sum = 0.f;
        #pragma unroll
        for (int j = 0; j < 8; j++) { v[j] = expf(v[j] - mx); sum += v[j]; }
        #pragma unroll
        for (int off = 16; off > 0; off >>= 1)
            sum += __shfl_xor_sync(0xffffffff, sum, off);
        float rinv = 1.0f / sum;
        __nv_bfloat16* prow = prow_base + (long)row * SS;
        #pragma unroll
        for (int j = 0; j < 8; j++)
            prow[lane + (j << 5)] = __float2bfloat16(v[j] * rinv);
    }
}

// ---------------- bf16 tensor-core GEMM, 3-stage cp.async pipeline --------
#define NSTAGE 3
template<int BM, bool TB>
struct SmemCfg {
    static constexpr int BROWS = TB ? 128 : 32;
    static constexpr int BCOLS = TB ? 40 : 136;
    static constexpr int A_ELEMS = NSTAGE * BM * 40;
    static constexpr int B_ELEMS = NSTAGE * BROWS * BCOLS;
    static constexpr int BYTES = (A_ELEMS + B_ELEMS) * 2;
};

template<int BM, bool TB, bool RELU, bool RES, bool OUTBF>
__global__ void __launch_bounds__(256)
gemm_bf(const __nv_bfloat16* __restrict__ A, const __nv_bfloat16* __restrict__ B,
        const float* __restrict__ bias, const float* __restrict__ res,
        float* __restrict__ Cf, __nv_bfloat16* __restrict__ Cb,
        int K, int lda, int ldb, int ldc,
        long sAb, long sAh, long sBb, long sBh, long sCb, long sCh)
{
    constexpr int IT = BM / 32;

    extern __shared__ __align__(16) char smem_raw[];
    __nv_bfloat16* As = (__nv_bfloat16*)smem_raw;
    __nv_bfloat16* Bs = As + SmemCfg<BM,TB>::A_ELEMS;

    int z = blockIdx.z;
    int bb = z >> 3, hh = z & 7;
    A += bb * sAb + hh * sAh;
    B += bb * sBb + hh * sBh;
    if (RES) res += bb * sCb + hh * sCh;
    long cbase = bb * sCb + hh * sCh;

    const int m0 = blockIdx.y * BM, n0 = blockIdx.x << 7;
    const int tid  = threadIdx.x;
    const int wid  = tid >> 5;
    const int lane = tid & 31;
    const int mbase = (wid >> 2) * (BM / 2);
    const int nbase = (wid & 3) * 32;
    const int lr  = ((lane >> 3) & 1) * 8 + (lane & 7);
    const int lc8 = (lane >> 4) * 8;

    uint32_t sAs = (uint32_t)__cvta_generic_to_shared(As);
    uint32_t sBs = (uint32_t)__cvta_generic_to_shared(Bs);

    float acc[IT][4][4];
    #pragma unroll
    for (int i = 0; i < IT; i++)
        #pragma unroll
        for (int j = 0; j < 4; j++)
            #pragma unroll
            for (int r = 0; r < 4; r++) acc[i][j][r] = 0.f;

    auto stage = [&](int s, int kb) {
        #pragma unroll
        for (int t = 0; t < BM / 64; t++) {
            int idx = tid + t * 256;
            int row = idx >> 2, ck = idx & 3;
            uint32_t d = sAs + 2u * ((s * BM + row) * 40 + ck * 8);
            cpa16(d, A + (long)(m0 + row) * lda + kb + ck * 8);
        }
        if (!TB) {
            #pragma unroll
            for (int t = 0; t < 2; t++) {
                int idx = tid + t * 256;
                int row = idx >> 4, ck = idx & 15;
                uint32_t d = sBs + 2u * ((s * 32 + row) * 136 + ck * 8);
                cpa16(d, B + (long)(kb + row) * ldb + n0 + ck * 8);
            }
        } else {
            #pragma unroll
            for (int t = 0; t < 2; t++) {
                int idx = tid + t * 256;
                int row = idx >> 2, ck = idx & 3;
                uint32_t d = sBs + 2u * ((s * 128 + row) * 40 + ck * 8);
                cpa16(d, B + (long)(n0 + row) * ldb + kb + ck * 8);
            }
        }
    };

    const int NIT = K >> 5;
    stage(0, 0);
    cp_commit();
    if (NIT > 1) stage(1, 32);
    cp_commit();

    int s = 0;
    for (int it = 0; it < NIT; it++) {
        cp_wait<1>();
        __syncthreads();

        #pragma unroll
        for (int ks = 0; ks < 32; ks += 16) {
            uint32_t a[IT][4], bf[4][2];
            #pragma unroll
            for (int i = 0; i < IT; i++) {
                uint32_t addr = sAs + 2u * ((s * BM + mbase + i * 16 + lr) * 40 + ks + lc8);
                ldsm4(a[i][0], a[i][1], a[i][2], a[i][3], addr);
            }
            #pragma unroll
            for (int jb = 0; jb < 2; jb++) {
                uint32_t r0, r1, r2, r3;
                if (!TB) {
                    uint32_t addr = sBs + 2u * ((s * 32 + ks + lr) * 136 + nbase + jb * 16 + lc8);
                    ldsm4t(r0, r1, r2, r3, addr);
                    bf[jb * 2 + 0][0] = r0; bf[jb * 2 + 0][1] = r1;
                    bf[jb * 2 + 1][0] = r2; bf[jb * 2 + 1][1] = r3;
                } else {
                    uint32_t addr = sBs + 2u * ((s * 128 + nbase + jb * 16 + lr) * 40 + ks + lc8);
                    ldsm4(r0, r1, r2, r3, addr);
                    bf[jb * 2 + 0][0] = r0; bf[jb * 2 + 0][1] = r2;
                    bf[jb * 2 + 1][0] = r1; bf[jb * 2 + 1][1] = r3;
                }
            }
            #pragma unroll
            for (int i = 0; i < IT; i++)
                #pragma unroll
                for (int j = 0; j < 4; j++)
                    mma_bf16(acc[i][j], a[i], bf[j]);
        }

        __syncthreads();
        if (it + 2 < NIT) {
            int sn = s + 2; if (sn >= NSTAGE) sn -= NSTAGE;
            stage(sn, (it + 2) << 5);
        }
        cp_commit();

        if (++s == NSTAGE) s = 0;
    }

    #pragma unroll
    for (int i = 0; i < IT; i++) {
        int r0 = m0 + mbase + i * 16 + (lane >> 2);
        #pragma unroll
        for (int j = 0; j < 4; j++) {
            int c0 = n0 + nbase + j * 8 + (lane & 3) * 2;
            float b0 = 0.f, b1 = 0.f;
            if (bias) { b0 = bias[c0]; b1 = bias[c0 + 1]; }
            float v00 = acc[i][j][0] + b0, v01 = acc[i][j][1] + b1;
            float v10 = acc[i][j][2] + b0, v11 = acc[i][j][3] + b1;
            if (RELU) {
                v00 = fmaxf(v00, 0.f); v01 = fmaxf(v01, 0.f);
                v10 = fmaxf(v10, 0.f); v11 = fmaxf(v11, 0.f);
            }
            if (RES) {
                v00 += res[(long)r0 * ldc + c0];
                v01 += res[(long)r0 * ldc + c0 + 1];
                v10 += res[(long)(r0 + 8) * ldc + c0];
                v11 += res[(long)(r0 + 8) * ldc + c0 + 1];
            }
            if (OUTBF) {
                *(__nv_bfloat162*)(Cb + cbase + (long)r0 * ldc + c0) =
                    __floats2bfloat162_rn(v00, v01);
                *(__nv_bfloat162*)(Cb + cbase + (long)(r0 + 8) * ldc + c0) =
                    __floats2bfloat162_rn(v10, v11);
            } else {
                *(float2*)(Cf + cbase + (long)r0 * ldc + c0)       = make_float2(v00, v01);
                *(float2*)(Cf + cbase + (long)(r0 + 8) * ldc + c0) = make_float2(v10, v11);
            }
        }
    }
}

// ---------------------------------------------------------------------------
extern "C" void kernel_launch(void* const* d_in, const int* in_sizes, int n_in,
                              void* d_out, int out_size)
{
    const float* data    = (const float*)d_in[0];
    const int*   attn_m  = (const int*)  d_in[1];
    const int*   view    = (const int*)  d_in[2];
    const float* seg_emb = (const float*)d_in[3];
    const float* Wq = (const float*)d_in[4];
    const float* bq = (const float*)d_in[5];
    const float* Wk = (const float*)d_in[6];
    const float* bk = (const float*)d_in[7];
    const float* Wv = (const float*)d_in[8];
    const float* bv = (const float*)d_in[9];
    const float* Wo = (const float*)d_in[10];
    const float* bo = (const float*)d_in[11];
    const float* W1 = (const float*)d_in[12];
    const float* b1 = (const float*)d_in[13];
    const float* W2 = (const float*)d_in[14];
    const float* b2 = (const float*)d_in[15];
    const float* alpha1 = (const float*)d_in[16];
    const float* bias1  = (const float*)d_in[17];
    const float* alpha2 = (const float*)d_in[18];
    const float* bias2  = (const float*)d_in[19];
    const float* alpha_f = (const float*)d_in[20];
    const float* bias_f  = (const float*)d_in[21];
    float* out = (float*)d_out;

    float *x;
    __nv_bfloat16 *x2b, *qkv, *sb, *ob, *fb;
    __nv_bfloat16 *wqkv, *wo, *w1, *w2;
    float *bqkv;
    cudaGetSymbolAddress((void**)&x,    g_x);
    cudaGetSymbolAddress((void**)&x2b,  g_x2b);
    cudaGetSymbolAddress((void**)&qkv,  g_qkv);
    cudaGetSymbolAddress((void**)&sb,   g_sb);
    cudaGetSymbolAddress((void**)&ob,   g_ob);
    cudaGetSymbolAddress((void**)&fb,   g_fb);
    cudaGetSymbolAddress((void**)&wqkv, g_wqkv);
    cudaGetSymbolAddress((void**)&bqkv, g_bqkv);
    cudaGetSymbolAddress((void**)&wo,   g_wo);
    cudaGetSymbolAddress((void**)&w1,   g_w1);
    cudaGetSymbolAddress((void**)&w2,   g_w2);

    constexpr int SM_NN128 = SmemCfg<128,false>::BYTES;   // 56832
    constexpr int SM_NN64  = SmemCfg<64, false>::BYTES;   // 41472
    constexpr int SM_ATT   = (ATT_MAIN_ELEMS * 2 > ATT_SMEM_BYTES)
                               ? ATT_MAIN_ELEMS * 2 : ATT_SMEM_BYTES;  // 135168
    cudaFuncSetAttribute(gemm_bf<128,false,false,false,true>,
        cudaFuncAttributeMaxDynamicSharedMemorySize, SM_NN128);
    cudaFuncSetAttribute(gemm_bf<128,false,true,false,true>,
        cudaFuncAttributeMaxDynamicSharedMemorySize, SM_NN128);
    cudaFuncSetAttribute(gemm_bf<64,false,false,true,false>,
        cudaFuncAttributeMaxDynamicSharedMemorySize, SM_NN64);
    cudaFuncSetAttribute(attn_scores_softmax,
        cudaFuncAttributeMaxDynamicSharedMemorySize, SM_ATT);

    cvt_weights<<<(6 * (WSZ / 4)) / 256, 256>>>(Wq, Wk, Wv, Wo, W1, W2);
    cvt_bias<<<(LNUM * QKVN + 255) / 256, 256>>>(bq, bk, bv);
    embed_kernel<<<(TOK * DMODEL + 255) / 256, 256>>>(data, seg_emb, view, x);

    const long sQb = (long)SS * QKVN;
    const long sQh = DKH;
    const long sSB = (long)HEADS * SS * SS;
    const long sSH = (long)SS * SS;
    const long sOb = (long)SS * HD;
    const long sOh = DKH;

    for (int i = 0; i < LNUM; i++) {
        layernorm_kernel<true><<<TOK, 256>>>(x, alpha1 + i * DMODEL, bias1 + i * DMODEL,
                                             nullptr, x2b);

        // fused QKV: [2048,512] @ [512,6144]
        dim3 gp(QKVN / 128, TOK / 128, 1);
        gemm_bf<128,false,false,false,true><<<gp, 256, SM_NN128>>>(
            x2b, wqkv + (long)i * DMODEL * QKVN, bqkv + (long)i * QKVN,
            nullptr, nullptr, qkv, DMODEL, DMODEL, QKVN, QKVN, 0,0,0,0,0,0);

        // fused scores + mask + softmax -> bf16 probs (single wave, 128 CTAs)
        dim3 gs(SS / 128, BB * HEADS);
        attn_scores_softmax<<<gs, 256, SM_ATT>>>(qkv, attn_m, sb);

        // o = P @ v (batched), bf16 out
        dim3 gv(DKH / 128, SS / 128, BB * HEADS);
        gemm_bf<128,false,false,false,true><<<gv, 256, SM_NN128>>>(
            sb, qkv + 2 * HD, nullptr, nullptr, nullptr, ob,
            SS, SS, QKVN, HD, sSB, sSH, sQb, sQh, sOb, sOh);

        // x = x + o @ Wo + bo
        dim3 go(DMODEL / 128, TOK / 64, 1);
        gemm_bf<64,false,false,true,false><<<go, 256, SM_NN64>>>(
            ob, wo + (long)i * HD * DMODEL, bo + (long)i * DMODEL,
            x, x, nullptr, HD, HD, DMODEL, DMODEL, 0,0,0,0,0,0);

        layernorm_kernel<true><<<TOK, 256>>>(x, alpha2 + i * DMODEL, bias2 + i * DMODEL,
                                             nullptr, x2b);

        // ff = relu(x2 @ W1 + b1)
        dim3 gf(DFFN / 128, TOK / 128, 1);
        gemm_bf<128,false,true,false,true><<<gf, 256, SM_NN128>>>(
            x2b, w1 + (long)i * DMODEL * DFFN, b1 + (long)i * DFFN,
            nullptr, nullptr, fb, DMODEL, DMODEL, DFFN, DFFN, 0,0,0,0,0,0);

        // x = x + ff @ W2 + b2
        gemm_bf<64,false,false,true,false><<<go, 256, SM_NN64>>>(
            fb, w2 + (long)i * DFFN * DMODEL, b2 + (long)i * DMODEL,
            x, x, nullptr, DFFN, DFFN, DMODEL, DMODEL, 0,0,0,0,0,0);
    }

    layernorm_kernel<false><<<TOK, 256>>>(x, alpha_f, bias_f, out, nullptr);
}

// round 7
// speedup vs baseline: 8.3253x; 1.1894x over previous
#include <cuda_runtime.h>
#include <cuda_bf16.h>
#include <math.h>
#include <stdint.h>

#define LNUM 4
#define DMODEL 512
#define HEADS 8
#define DKH 256
#define DFFN 2048
#define BB 8
#define SS 256
#define HD (HEADS*DKH)          // 2048
#define TOK (BB*SS)             // 2048
#define QKVN (3*HD)             // 6144
#define EPS 1e-6f

// ---------------- scratch (device globals; no allocations) ----------------
__device__ float g_x [TOK*DMODEL];          // fp32 residual stream

__device__ __nv_bfloat16 g_x2b [TOK*DMODEL];
__device__ __nv_bfloat16 g_qkv [TOK*QKVN];  // packed q|k|v
__device__ __nv_bfloat16 g_sb  [BB*HEADS*SS*SS];   // bf16 probs
__device__ __nv_bfloat16 g_ob  [TOK*HD];
__device__ __nv_bfloat16 g_fb  [TOK*DFFN];
// bf16 weights
#define WSZ 4194304                          // 4*512*2048
__device__ __nv_bfloat16 g_wqkv[LNUM*DMODEL*QKVN];   // packed per-layer [512][6144]
__device__ float         g_bqkv[LNUM*QKVN];
__device__ __nv_bfloat16 g_wo[WSZ];
__device__ __nv_bfloat16 g_w1[WSZ];
__device__ __nv_bfloat16 g_w2[WSZ];

// ---------------- PTX helpers ---------------------------------------------
__device__ __forceinline__ void cpa16(uint32_t dst, const void* src) {
    asm volatile("cp.async.cg.shared.global [%0], [%1], 16;" :: "r"(dst), "l"(src) : "memory");
}
__device__ __forceinline__ void cp_commit() {
    asm volatile("cp.async.commit_group;" ::: "memory");
}
template<int N>
__device__ __forceinline__ void cp_wait() {
    asm volatile("cp.async.wait_group %0;" :: "n"(N) : "memory");
}
__device__ __forceinline__ void ldsm4(uint32_t& r0, uint32_t& r1, uint32_t& r2, uint32_t& r3, uint32_t a) {
    asm volatile("ldmatrix.sync.aligned.m8n8.x4.shared.b16 {%0,%1,%2,%3}, [%4];"
                 : "=r"(r0), "=r"(r1), "=r"(r2), "=r"(r3) : "r"(a));
}
__device__ __forceinline__ void ldsm4t(uint32_t& r0, uint32_t& r1, uint32_t& r2, uint32_t& r3, uint32_t a) {
    asm volatile("ldmatrix.sync.aligned.m8n8.x4.trans.shared.b16 {%0,%1,%2,%3}, [%4];"
                 : "=r"(r0), "=r"(r1), "=r"(r2), "=r"(r3) : "r"(a));
}
__device__ __forceinline__ void mma_bf16(float* d, const uint32_t* a, const uint32_t* b) {
    asm volatile("mma.sync.aligned.m16n8k16.row.col.f32.bf16.bf16.f32 "
                 "{%0,%1,%2,%3}, {%4,%5,%6,%7}, {%8,%9}, {%0,%1,%2,%3};"
                 : "+f"(d[0]), "+f"(d[1]), "+f"(d[2]), "+f"(d[3])
                 : "r"(a[0]), "r"(a[1]), "r"(a[2]), "r"(a[3]), "r"(b[0]), "r"(b[1]));
}

// ---------------- weight fp32 -> bf16 (once per launch) -------------------
__global__ void cvt_weights(const float* __restrict__ wq, const float* __restrict__ wk,
                            const float* __restrict__ wv, const float* __restrict__ wo,
                            const float* __restrict__ w1, const float* __restrict__ w2)
{
    long i4 = (long)blockIdx.x * blockDim.x + threadIdx.x;
    int which = (int)(i4 >> 20);
    long off = (i4 & ((1L << 20) - 1)) << 2;
    const float* s;
    __nv_bfloat16* d;
    long doff = off;
    if (which < 3) {
        s = (which == 0) ? wq : (which == 1) ? wk : wv;
        long l   = off / ((long)DMODEL * HD);
        long win = off - l * (long)DMODEL * HD;
        long row = win / HD;
        long col = win - row * HD;
        d = g_wqkv;
        doff = l * (long)DMODEL * QKVN + row * QKVN + which * HD + col;
    } else {
        s = (which == 3) ? wo : (which == 4) ? w1 : w2;
        d = (which == 3) ? g_wo : (which == 4) ? g_w1 : g_w2;
    }
    float4 v = *(const float4*)(s + off);
    *(__nv_bfloat162*)(d + doff)     = __floats2bfloat162_rn(v.x, v.y);
    *(__nv_bfloat162*)(d + doff + 2) = __floats2bfloat162_rn(v.z, v.w);
}

__global__ void cvt_bias(const float* __restrict__ bq, const float* __restrict__ bk,
                         const float* __restrict__ bv)
{
    int idx = blockIdx.x * blockDim.x + threadIdx.x;
    if (idx >= LNUM * QKVN) return;
    int l = idx / QKVN;
    int c = idx - l * QKVN;
    int which = c >> 11;
    int col = c & (HD - 1);
    const float* s = (which == 0) ? bq : (which == 1) ? bk : bv;
    g_bqkv[idx] = s[l * HD + col];
}

// ---------------- embed ----------------------------------------------------
__global__ void embed_kernel(const float* __restrict__ data,
                             const float* __restrict__ seg_emb,
                             const int* __restrict__ view,
                             float* __restrict__ x)
{
    int idx = blockIdx.x * blockDim.x + threadIdx.x;
    if (idx >= TOK * DMODEL) return;
    int c = idx & (DMODEL - 1);
    int s = (idx >> 9) & (SS - 1);
    float inv = exp2f(-(float)c * (1.0f / 32.0f));
    float arg = (float)s * inv;
    float pe  = (c & 1) ? cosf(arg) : sinf(arg);
    int seg_off = view[0] * SS * DMODEL + c;
    x[idx] = data[idx] * sqrtf((float)DMODEL) + pe + seg_emb[seg_off];
}

// ---------------- layernorm: warp-per-row, shuffle-only -------------------
// 256 threads = 8 warps = 8 rows per CTA; grid = TOK/8.
template<bool OB>
__global__ void layernorm_kernel(const float* __restrict__ x,
                                 const float* __restrict__ alpha,
                                 const float* __restrict__ beta,
                                 float* __restrict__ outf,
                                 __nv_bfloat16* __restrict__ outb)
{
    const int wid = threadIdx.x >> 5, lane = threadIdx.x & 31;
    const int row = blockIdx.x * 8 + wid;
    const float4* p4 = (const float4*)(x + (long)row * DMODEL);

    float4 v[4];
    float s = 0.f, sq = 0.f;
    #pragma unroll
    for (int j = 0; j < 4; j++) {
        v[j] = p4[lane + j * 32];
        s  += v[j].x + v[j].y + v[j].z + v[j].w;
        sq += v[j].x * v[j].x + v[j].y * v[j].y + v[j].z * v[j].z + v[j].w * v[j].w;
    }
    #pragma unroll
    for (int off = 16; off > 0; off >>= 1) {
        s  += __shfl_xor_sync(0xffffffff, s,  off);
        sq += __shfl_xor_sync(0xffffffff, sq, off);
    }

    float mean = s * (1.0f / DMODEL);
    float var  = (sq - (float)DMODEL * mean * mean) * (1.0f / (DMODEL - 1));
    var = fmaxf(var, 0.f);
    float rinv = 1.0f / (sqrtf(var) + EPS);

    const float4* a4 = (const float4*)alpha;
    const float4* b4 = (const float4*)beta;
    #pragma unroll
    for (int j = 0; j < 4; j++) {
        float4 av = a4[lane + j * 32];
        float4 bv = b4[lane + j * 32];
        float ox = av.x * (v[j].x - mean) * rinv + bv.x;
        float oy = av.y * (v[j].y - mean) * rinv + bv.y;
        float oz = av.z * (v[j].z - mean) * rinv + bv.z;
        float ow = av.w * (v[j].w - mean) * rinv + bv.w;
        long e = (long)row * DMODEL + (lane + j * 32) * 4;
        if (OB) {
            __nv_bfloat162 lo = __floats2bfloat162_rn(ox, oy);
            __nv_bfloat162 hi = __floats2bfloat162_rn(oz, ow);
            *(__nv_bfloat162*)(outb + e)     = lo;
            *(__nv_bfloat162*)(outb + e + 2) = hi;
        } else {
            *(float4*)(outf + e) = make_float4(ox, oy, oz, ow);
        }
    }
}

// ---------------- fused scores GEMM + mask + softmax ----------------------
// CTA: 128 q-rows x 256 keys (full row), one (b,h) per blockIdx.y.
#define ATT_NST 4
#define ATT_MAIN_ELEMS (ATT_NST*128*40 + ATT_NST*256*40)        // bf16 elems
#define ATT_SMEM_BYTES (128*264*4)                               // epilogue S (bigger)

__global__ void __launch_bounds__(256)
attn_scores_softmax(const __nv_bfloat16* __restrict__ qkv,
                    const int* __restrict__ attn_m,
                    __nv_bfloat16* __restrict__ sb)
{
    extern __shared__ __align__(16) char smem_raw[];
    __nv_bfloat16* As = (__nv_bfloat16*)smem_raw;        // [4][128][40]
    __nv_bfloat16* Bs = As + ATT_NST * 128 * 40;         // [4][256][40]
    float* Ssm = (float*)smem_raw;                        // [128][264] (reuse)
    __shared__ int msk[SS];

    const int z = blockIdx.y;            // b*8+h
    const int b = z >> 3, h = z & 7;
    const int m0 = blockIdx.x << 7;
    const long sQb = (long)SS * QKVN;
    const __nv_bfloat16* A = qkv + b * sQb + (long)h * DKH + (long)m0 * QKVN;
    const __nv_bfloat16* B = qkv + HD + b * sQb + (long)h * DKH;

    const int tid  = threadIdx.x;
    const int wid  = tid >> 5;
    const int lane = tid & 31;
    const int mbase = (wid >> 2) * 64;
    const int nbase = (wid & 3) * 64;
    const int lr  = ((lane >> 3) & 1) * 8 + (lane & 7);
    const int lc8 = (lane >> 4) * 8;
    const int lg = lane >> 2, lt = lane & 3;

    if (tid < SS) msk[tid] = attn_m[b * SS + tid];

    uint32_t sAs = (uint32_t)__cvta_generic_to_shared(As);
    uint32_t sBs = (uint32_t)__cvta_generic_to_shared(Bs);

    float acc[4][8][4];
    #pragma unroll
    for (int i = 0; i < 4; i++)
        #pragma unroll
        for (int j = 0; j < 8; j++)
            #pragma unroll
            for (int r = 0; r < 4; r++) acc[i][j][r] = 0.f;

    auto stage = [&](int s, int kb) {
        #pragma unroll
        for (int t = 0; t < 2; t++) {
            int idx = tid + t * 256;
            int row = idx >> 2, ck = idx & 3;
            uint32_t d = sAs + 2u * ((s * 128 + row) * 40 + ck * 8);
            cpa16(d, A + (long)row * QKVN + kb + ck * 8);
        }
        #pragma unroll
        for (int t = 0; t < 4; t++) {
            int idx = tid + t * 256;
            int row = idx >> 2, ck = idx & 3;
            uint32_t d = sBs + 2u * ((s * 256 + row) * 40 + ck * 8);
            cpa16(d, B + (long)row * QKVN + kb + ck * 8);
        }
    };

    const int NIT = DKH / 32;     // 8
    stage(0, 0);  cp_commit();
    stage(1, 32); cp_commit();
    stage(2, 64); cp_commit();

    for (int it = 0; it < NIT; it++) {
        int s = it & 3;
        cp_wait<2>();
        __syncthreads();

        #pragma unroll
        for (int ks = 0; ks < 32; ks += 16) {
            uint32_t a[4][4], bf[8][2];
            #pragma unroll
            for (int i = 0; i < 4; i++) {
                uint32_t addr = sAs + 2u * ((s * 128 + mbase + i * 16 + lr) * 40 + ks + lc8);
                ldsm4(a[i][0], a[i][1], a[i][2], a[i][3], addr);
            }
            #pragma unroll
            for (int jb = 0; jb < 4; jb++) {
                uint32_t r0, r1, r2, r3;
                uint32_t addr = sBs + 2u * ((s * 256 + nbase + jb * 16 + lr) * 40 + ks + lc8);
                ldsm4(r0, r1, r2, r3, addr);
                bf[jb * 2 + 0][0] = r0; bf[jb * 2 + 0][1] = r2;
                bf[jb * 2 + 1][0] = r1; bf[jb * 2 + 1][1] = r3;
            }
            #pragma unroll
            for (int i = 0; i < 4; i++)
                #pragma unroll
                for (int j = 0; j < 8; j++)
                    mma_bf16(acc[i][j], a[i], bf[j]);
        }

        if (it + 3 < NIT) stage((it + 3) & 3, (it + 3) << 5);
        cp_commit();
    }

    // ---- epilogue: S -> smem, per-row masked softmax, bf16 out ----
    cp_wait<0>();
    __syncthreads();

    #pragma unroll
    for (int i = 0; i < 4; i++) {
        int r0 = mbase + i * 16 + lg;
        #pragma unroll
        for (int j = 0; j < 8; j++) {
            int c0 = nbase + j * 8 + lt * 2;
            Ssm[r0 * 264 + c0]           = acc[i][j][0];
            Ssm[r0 * 264 + c0 + 1]       = acc[i][j][1];
            Ssm[(r0 + 8) * 264 + c0]     = acc[i][j][2];
            Ssm[(r0 + 8) * 264 + c0 + 1] = acc[i][j][3];
        }
    }
    __syncthreads();

    __nv_bfloat16* prow_base = sb + ((long)z * SS + m0) * SS;
    #pragma unroll
    for (int r = 0; r < 16; r++) {
        int row = wid * 16 + r;
        const float* srow = Ssm + row * 264;
        float v[8];
        float mx = -1e30f;
        #pragma unroll
        for (int j = 0; j < 8; j++) {
            int col = lane + (j << 5);
            float val = msk[col] ? -1e9f : srow[col] * 0.0625f;
            v[j] = val;
            mx = fmaxf(mx, val);
        }
        #pragma unroll
        for (int off = 16; off > 0; off >>= 1)
            mx = fmaxf(mx, __shfl_xor_sync(0xffffffff, mx, off));
        float sum = 0.f;
        #pragma unroll
        for (int j = 0; j < 8; j++) { v[j] = expf(v[j] - mx); sum += v[j]; }
        #pragma unroll
        for (int off = 16; off > 0; off >>= 1)
            sum += __shfl_xor_sync(0xffffffff, sum, off);
        float rinv = 1.0f / sum;
        __nv_bfloat16* prow = prow_base + (long)row * SS;
        #pragma unroll
        for (int j = 0; j < 8; j++)
            prow[lane + (j << 5)] = __float2bfloat16(v[j] * rinv);
    }
}

// ---------------- bf16 tensor-core GEMM, 4-stage cp.async pipeline --------
#define NSTAGE 4
template<int BM, bool TB>
struct SmemCfg {
    static constexpr int BROWS = TB ? 128 : 32;
    static constexpr int BCOLS = TB ? 40 : 136;
    static constexpr int A_ELEMS = NSTAGE * BM * 40;
    static constexpr int B_ELEMS = NSTAGE * BROWS * BCOLS;
    static constexpr int BYTES = (A_ELEMS + B_ELEMS) * 2;
};

template<int BM, bool TB, bool RELU, bool RES, bool OUTBF>
__global__ void __launch_bounds__(256)
gemm_bf(const __nv_bfloat16* __restrict__ A, const __nv_bfloat16* __restrict__ B,
        const float* __restrict__ bias, const float* __restrict__ res,
        float* __restrict__ Cf, __nv_bfloat16* __restrict__ Cb,
        int K, int lda, int ldb, int ldc,
        long sAb, long sAh, long sBb, long sBh, long sCb, long sCh)
{
    constexpr int IT = BM / 32;

    extern __shared__ __align__(16) char smem_raw[];
    __nv_bfloat16* As = (__nv_bfloat16*)smem_raw;
    __nv_bfloat16* Bs = As + SmemCfg<BM,TB>::A_ELEMS;

    int z = blockIdx.z;
    int bb = z >> 3, hh = z & 7;
    A += bb * sAb + hh * sAh;
    B += bb * sBb + hh * sBh;
    if (RES) res += bb * sCb + hh * sCh;
    long cbase = bb * sCb + hh * sCh;

    const int m0 = blockIdx.y * BM, n0 = blockIdx.x << 7;
    const int tid  = threadIdx.x;
    const int wid  = tid >> 5;
    const int lane = tid & 31;
    const int mbase = (wid >> 2) * (BM / 2);
    const int nbase = (wid & 3) * 32;
    const int lr  = ((lane >> 3) & 1) * 8 + (lane & 7);
    const int lc8 = (lane >> 4) * 8;

    uint32_t sAs = (uint32_t)__cvta_generic_to_shared(As);
    uint32_t sBs = (uint32_t)__cvta_generic_to_shared(Bs);

    float acc[IT][4][4];
    #pragma unroll
    for (int i = 0; i < IT; i++)
        #pragma unroll
        for (int j = 0; j < 4; j++)
            #pragma unroll
            for (int r = 0; r < 4; r++) acc[i][j][r] = 0.f;

    auto stage = [&](int s, int kb) {
        #pragma unroll
        for (int t = 0; t < BM / 64; t++) {
            int idx = tid + t * 256;
            int row = idx >> 2, ck = idx & 3;
            uint32_t d = sAs + 2u * ((s * BM + row) * 40 + ck * 8);
            cpa16(d, A + (long)(m0 + row) * lda + kb + ck * 8);
        }
        if (!TB) {
            #pragma unroll
            for (int t = 0; t < 2; t++) {
                int idx = tid + t * 256;
                int row = idx >> 4, ck = idx & 15;
                uint32_t d = sBs + 2u * ((s * 32 + row) * 136 + ck * 8);
                cpa16(d, B + (long)(kb + row) * ldb + n0 + ck * 8);
            }
        } else {
            #pragma unroll
            for (int t = 0; t < 2; t++) {
                int idx = tid + t * 256;
                int row = idx >> 2, ck = idx & 3;
                uint32_t d = sBs + 2u * ((s * 128 + row) * 40 + ck * 8);
                cpa16(d, B + (long)(n0 + row) * ldb + kb + ck * 8);
            }
        }
    };

    const int NIT = K >> 5;     // >= 16 for all call sites
    stage(0, 0);  cp_commit();
    stage(1, 32); cp_commit();
    stage(2, 64); cp_commit();

    for (int it = 0; it < NIT; it++) {
        int s = it & 3;
        cp_wait<2>();
        __syncthreads();

        #pragma unroll
        for (int ks = 0; ks < 32; ks += 16) {
            uint32_t a[IT][4], bf[4][2];
            #pragma unroll
            for (int i = 0; i < IT; i++) {
                uint32_t addr = sAs + 2u * ((s * BM + mbase + i * 16 + lr) * 40 + ks + lc8);
                ldsm4(a[i][0], a[i][1], a[i][2], a[i][3], addr);
            }
            #pragma unroll
            for (int jb = 0; jb < 2; jb++) {
                uint32_t r0, r1, r2, r3;
                if (!TB) {
                    uint32_t addr = sBs + 2u * ((s * 32 + ks + lr) * 136 + nbase + jb * 16 + lc8);
                    ldsm4t(r0, r1, r2, r3, addr);
                    bf[jb * 2 + 0][0] = r0; bf[jb * 2 + 0][1] = r1;
                    bf[jb * 2 + 1][0] = r2; bf[jb * 2 + 1][1] = r3;
                } else {
                    uint32_t addr = sBs + 2u * ((s * 128 + nbase + jb * 16 + lr) * 40 + ks + lc8);
                    ldsm4(r0, r1, r2, r3, addr);
                    bf[jb * 2 + 0][0] = r0; bf[jb * 2 + 0][1] = r2;
                    bf[jb * 2 + 1][0] = r1; bf[jb * 2 + 1][1] = r3;
                }
            }
            #pragma unroll
            for (int i = 0; i < IT; i++)
                #pragma unroll
                for (int j = 0; j < 4; j++)
                    mma_bf16(acc[i][j], a[i], bf[j]);
        }

        if (it + 3 < NIT) stage((it + 3) & 3, (it + 3) << 5);
        cp_commit();
    }

    #pragma unroll
    for (int i = 0; i < IT; i++) {
        int r0 = m0 + mbase + i * 16 + (lane >> 2);
        #pragma unroll
        for (int j = 0; j < 4; j++) {
            int c0 = n0 + nbase + j * 8 + (lane & 3) * 2;
            float b0 = 0.f, b1 = 0.f;
            if (bias) { b0 = bias[c0]; b1 = bias[c0 + 1]; }
            float v00 = acc[i][j][0] + b0, v01 = acc[i][j][1] + b1;
            float v10 = acc[i][j][2] + b0, v11 = acc[i][j][3] + b1;
            if (RELU) {
                v00 = fmaxf(v00, 0.f); v01 = fmaxf(v01, 0.f);
                v10 = fmaxf(v10, 0.f); v11 = fmaxf(v11, 0.f);
            }
            if (RES) {
                v00 += res[(long)r0 * ldc + c0];
                v01 += res[(long)r0 * ldc + c0 + 1];
                v10 += res[(long)(r0 + 8) * ldc + c0];
                v11 += res[(long)(r0 + 8) * ldc + c0 + 1];
            }
            if (OUTBF) {
                *(__nv_bfloat162*)(Cb + cbase + (long)r0 * ldc + c0) =
                    __floats2bfloat162_rn(v00, v01);
                *(__nv_bfloat162*)(Cb + cbase + (long)(r0 + 8) * ldc + c0) =
                    __floats2bfloat162_rn(v10, v11);
            } else {
                *(float2*)(Cf + cbase + (long)r0 * ldc + c0)       = make_float2(v00, v01);
                *(float2*)(Cf + cbase + (long)(r0 + 8) * ldc + c0) = make_float2(v10, v11);
            }
        }
    }
}

// ---------------------------------------------------------------------------
extern "C" void kernel_launch(void* const* d_in, const int* in_sizes, int n_in,
                              void* d_out, int out_size)
{
    const float* data    = (const float*)d_in[0];
    const int*   attn_m  = (const int*)  d_in[1];
    const int*   view    = (const int*)  d_in[2];
    const float* seg_emb = (const float*)d_in[3];
    const float* Wq = (const float*)d_in[4];
    const float* bq = (const float*)d_in[5];
    const float* Wk = (const float*)d_in[6];
    const float* bk = (const float*)d_in[7];
    const float* Wv = (const float*)d_in[8];
    const float* bv = (const float*)d_in[9];
    const float* Wo = (const float*)d_in[10];
    const float* bo = (const float*)d_in[11];
    const float* W1 = (const float*)d_in[12];
    const float* b1 = (const float*)d_in[13];
    const float* W2 = (const float*)d_in[14];
    const float* b2 = (const float*)d_in[15];
    const float* alpha1 = (const float*)d_in[16];
    const float* bias1  = (const float*)d_in[17];
    const float* alpha2 = (const float*)d_in[18];
    const float* bias2  = (const float*)d_in[19];
    const float* alpha_f = (const float*)d_in[20];
    const float* bias_f  = (const float*)d_in[21];
    float* out = (float*)d_out;

    float *x;
    __nv_bfloat16 *x2b, *qkv, *sb, *ob, *fb;
    __nv_bfloat16 *wqkv, *wo, *w1, *w2;
    float *bqkv;
    cudaGetSymbolAddress((void**)&x,    g_x);
    cudaGetSymbolAddress((void**)&x2b,  g_x2b);
    cudaGetSymbolAddress((void**)&qkv,  g_qkv);
    cudaGetSymbolAddress((void**)&sb,   g_sb);
    cudaGetSymbolAddress((void**)&ob,   g_ob);
    cudaGetSymbolAddress((void**)&fb,   g_fb);
    cudaGetSymbolAddress((void**)&wqkv, g_wqkv);
    cudaGetSymbolAddress((void**)&bqkv, g_bqkv);
    cudaGetSymbolAddress((void**)&wo,   g_wo);
    cudaGetSymbolAddress((void**)&w1,   g_w1);
    cudaGetSymbolAddress((void**)&w2,   g_w2);

    constexpr int SM_NN128 = SmemCfg<128,false>::BYTES;   // 75776
    constexpr int SM_NN64  = SmemCfg<64, false>::BYTES;   // 55296
    constexpr int SM_ATT   = (ATT_MAIN_ELEMS * 2 > ATT_SMEM_BYTES)
                               ? ATT_MAIN_ELEMS * 2 : ATT_SMEM_BYTES;  // 135168
    cudaFuncSetAttribute(gemm_bf<128,false,false,false,true>,
        cudaFuncAttributeMaxDynamicSharedMemorySize, SM_NN128);
    cudaFuncSetAttribute(gemm_bf<128,false,true,false,true>,
        cudaFuncAttributeMaxDynamicSharedMemorySize, SM_NN128);
    cudaFuncSetAttribute(gemm_bf<64,false,false,true,false>,
        cudaFuncAttributeMaxDynamicSharedMemorySize, SM_NN64);
    cudaFuncSetAttribute(attn_scores_softmax,
        cudaFuncAttributeMaxDynamicSharedMemorySize, SM_ATT);

    cvt_weights<<<(6 * (WSZ / 4)) / 256, 256>>>(Wq, Wk, Wv, Wo, W1, W2);
    cvt_bias<<<(LNUM * QKVN + 255) / 256, 256>>>(bq, bk, bv);
    embed_kernel<<<(TOK * DMODEL + 255) / 256, 256>>>(data, seg_emb, view, x);

    const long sQb = (long)SS * QKVN;
    const long sQh = DKH;
    const long sSB = (long)HEADS * SS * SS;
    const long sSH = (long)SS * SS;
    const long sOb = (long)SS * HD;
    const long sOh = DKH;

    for (int i = 0; i < LNUM; i++) {
        layernorm_kernel<true><<<TOK / 8, 256>>>(x, alpha1 + i * DMODEL, bias1 + i * DMODEL,
                                                 nullptr, x2b);

        // fused QKV: [2048,512] @ [512,6144]
        dim3 gp(QKVN / 128, TOK / 128, 1);
        gemm_bf<128,false,false,false,true><<<gp, 256, SM_NN128>>>(
            x2b, wqkv + (long)i * DMODEL * QKVN, bqkv + (long)i * QKVN,
            nullptr, nullptr, qkv, DMODEL, DMODEL, QKVN, QKVN, 0,0,0,0,0,0);

        // fused scores + mask + softmax -> bf16 probs
        dim3 gs(SS / 128, BB * HEADS);
        attn_scores_softmax<<<gs, 256, SM_ATT>>>(qkv, attn_m, sb);

        // o = P @ v (batched), bf16 out
        dim3 gv(DKH / 128, SS / 128, BB * HEADS);
        gemm_bf<128,false,false,false,true><<<gv, 256, SM_NN128>>>(
            sb, qkv + 2 * HD, nullptr, nullptr, nullptr, ob,
            SS, SS, QKVN, HD, sSB, sSH, sQb, sQh, sOb, sOh);

        // x = x + o @ Wo + bo
        dim3 go(DMODEL / 128, TOK / 64, 1);
        gemm_bf<64,false,false,true,false><<<go, 256, SM_NN64>>>(
            ob, wo + (long)i * HD * DMODEL, bo + (long)i * DMODEL,
            x, x, nullptr, HD, HD, DMODEL, DMODEL, 0,0,0,0,0,0);

        layernorm_kernel<true><<<TOK / 8, 256>>>(x, alpha2 + i * DMODEL, bias2 + i * DMODEL,
                                                 nullptr, x2b);

        // ff = relu(x2 @ W1 + b1)
        dim3 gf(DFFN / 128, TOK / 128, 1);
        gemm_bf<128,false,true,false,true><<<gf, 256, SM_NN128>>>(
            x2b, w1 + (long)i * DMODEL * DFFN, b1 + (long)i * DFFN,
            nullptr, nullptr, fb, DMODEL, DMODEL, DFFN, DFFN, 0,0,0,0,0,0);

        // x = x + ff @ W2 + b2
        gemm_bf<64,false,false,true,false><<<go, 256, SM_NN64>>>(
            fb, w2 + (long)i * DFFN * DMODEL, b2 + (long)i * DMODEL,
            x, x, nullptr, DFFN, DFFN, DMODEL, DMODEL, 0,0,0,0,0,0);
    }

    layernorm_kernel<false><<<TOK / 8, 256>>>(x, alpha_f, bias_f, out, nullptr);
}

// round 9
// speedup vs baseline: 8.6313x; 1.0368x over previous
#include <cuda_runtime.h>
#include <cuda_bf16.h>
#include <math.h>
#include <stdint.h>

#define LNUM 4
#define DMODEL 512
#define HEADS 8
#define DKH 256
#define DFFN 2048
#define BB 8
#define SS 256
#define HD (HEADS*DKH)          // 2048
#define TOK (BB*SS)             // 2048
#define QKVN (3*HD)             // 6144
#define EPS 1e-6f

// ---------------- scratch (device globals; no allocations) ----------------
__device__ float g_x [TOK*DMODEL];          // fp32 residual stream

__device__ __nv_bfloat16 g_x2b [TOK*DMODEL];
__device__ __nv_bfloat16 g_qkv [TOK*QKVN];  // packed q|k|v
__device__ __nv_bfloat16 g_ob  [TOK*HD];
__device__ __nv_bfloat16 g_fb  [TOK*DFFN];
// bf16 weights
#define WSZ 4194304                          // 4*512*2048
__device__ __nv_bfloat16 g_wqkv[LNUM*DMODEL*QKVN];   // packed per-layer [512][6144]
__device__ float         g_bqkv[LNUM*QKVN];
__device__ __nv_bfloat16 g_wo[WSZ];
__device__ __nv_bfloat16 g_w1[WSZ];
__device__ __nv_bfloat16 g_w2[WSZ];

// ---------------- PTX helpers ---------------------------------------------
__device__ __forceinline__ void cpa16(uint32_t dst, const void* src) {
    asm volatile("cp.async.cg.shared.global [%0], [%1], 16;" :: "r"(dst), "l"(src) : "memory");
}
__device__ __forceinline__ void cp_commit() {
    asm volatile("cp.async.commit_group;" ::: "memory");
}
template<int N>
__device__ __forceinline__ void cp_wait() {
    asm volatile("cp.async.wait_group %0;" :: "n"(N) : "memory");
}
__device__ __forceinline__ void ldsm4(uint32_t& r0, uint32_t& r1, uint32_t& r2, uint32_t& r3, uint32_t a) {
    asm volatile("ldmatrix.sync.aligned.m8n8.x4.shared.b16 {%0,%1,%2,%3}, [%4];"
                 : "=r"(r0), "=r"(r1), "=r"(r2), "=r"(r3) : "r"(a));
}
__device__ __forceinline__ void ldsm4t(uint32_t& r0, uint32_t& r1, uint32_t& r2, uint32_t& r3, uint32_t a) {
    asm volatile("ldmatrix.sync.aligned.m8n8.x4.trans.shared.b16 {%0,%1,%2,%3}, [%4];"
                 : "=r"(r0), "=r"(r1), "=r"(r2), "=r"(r3) : "r"(a));
}
__device__ __forceinline__ void mma_bf16(float* d, const uint32_t* a, const uint32_t* b) {
    asm volatile("mma.sync.aligned.m16n8k16.row.col.f32.bf16.bf16.f32 "
                 "{%0,%1,%2,%3}, {%4,%5,%6,%7}, {%8,%9}, {%0,%1,%2,%3};"
                 : "+f"(d[0]), "+f"(d[1]), "+f"(d[2]), "+f"(d[3])
                 : "r"(a[0]), "r"(a[1]), "r"(a[2]), "r"(a[3]), "r"(b[0]), "r"(b[1]));
}

// ---------------- weight fp32 -> bf16 (once per launch) -------------------
__global__ void cvt_weights(const float* __restrict__ wq, const float* __restrict__ wk,
                            const float* __restrict__ wv, const float* __restrict__ wo,
                            const float* __restrict__ w1, const float* __restrict__ w2)
{
    long i4 = (long)blockIdx.x * blockDim.x + threadIdx.x;
    int which = (int)(i4 >> 20);
    long off = (i4 & ((1L << 20) - 1)) << 2;
    const float* s;
    __nv_bfloat16* d;
    long doff = off;
    if (which < 3) {
        s = (which == 0) ? wq : (which == 1) ? wk : wv;
        long l   = off / ((long)DMODEL * HD);
        long win = off - l * (long)DMODEL * HD;
        long row = win / HD;
        long col = win - row * HD;
        d = g_wqkv;
        doff = l * (long)DMODEL * QKVN + row * QKVN + which * HD + col;
    } else {
        s = (which == 3) ? wo : (which == 4) ? w1 : w2;
        d = (which == 3) ? g_wo : (which == 4) ? g_w1 : g_w2;
    }
    float4 v = *(const float4*)(s + off);
    *(__nv_bfloat162*)(d + doff)     = __floats2bfloat162_rn(v.x, v.y);
    *(__nv_bfloat162*)(d + doff + 2) = __floats2bfloat162_rn(v.z, v.w);
}

__global__ void cvt_bias(const float* __restrict__ bq, const float* __restrict__ bk,
                         const float* __restrict__ bv)
{
    int idx = blockIdx.x * blockDim.x + threadIdx.x;
    if (idx >= LNUM * QKVN) return;
    int l = idx / QKVN;
    int c = idx - l * QKVN;
    int which = c >> 11;
    int col = c & (HD - 1);
    const float* s = (which == 0) ? bq : (which == 1) ? bk : bv;
    g_bqkv[idx] = s[l * HD + col];
}

// ---------------- embed ----------------------------------------------------
__global__ void embed_kernel(const float* __restrict__ data,
                             const float* __restrict__ seg_emb,
                             const int* __restrict__ view,
                             float* __restrict__ x)
{
    int idx = blockIdx.x * blockDim.x + threadIdx.x;
    if (idx >= TOK * DMODEL) return;
    int c = idx & (DMODEL - 1);
    int s = (idx >> 9) & (SS - 1);
    float inv = exp2f(-(float)c * (1.0f / 32.0f));
    float arg = (float)s * inv;
    float pe  = (c & 1) ? cosf(arg) : sinf(arg);
    int seg_off = view[0] * SS * DMODEL + c;
    x[idx] = data[idx] * sqrtf((float)DMODEL) + pe + seg_emb[seg_off];
}

// ---------------- layernorm: warp-per-row, shuffle-only -------------------
template<bool OB>
__global__ void layernorm_kernel(const float* __restrict__ x,
                                 const float* __restrict__ alpha,
                                 const float* __restrict__ beta,
                                 float* __restrict__ outf,
                                 __nv_bfloat16* __restrict__ outb)
{
    const int wid = threadIdx.x >> 5, lane = threadIdx.x & 31;
    const int row = blockIdx.x * 8 + wid;
    const float4* p4 = (const float4*)(x + (long)row * DMODEL);

    float4 v[4];
    float s = 0.f, sq = 0.f;
    #pragma unroll
    for (int j = 0; j < 4; j++) {
        v[j] = p4[lane + j * 32];
        s  += v[j].x + v[j].y + v[j].z + v[j].w;
        sq += v[j].x * v[j].x + v[j].y * v[j].y + v[j].z * v[j].z + v[j].w * v[j].w;
    }
    #pragma unroll
    for (int off = 16; off > 0; off >>= 1) {
        s  += __shfl_xor_sync(0xffffffff, s,  off);
        sq += __shfl_xor_sync(0xffffffff, sq, off);
    }

    float mean = s * (1.0f / DMODEL);
    float var  = (sq - (float)DMODEL * mean * mean) * (1.0f / (DMODEL - 1));
    var = fmaxf(var, 0.f);
    float rinv = 1.0f / (sqrtf(var) + EPS);

    const float4* a4 = (const float4*)alpha;
    const float4* b4 = (const float4*)beta;
    #pragma unroll
    for (int j = 0; j < 4; j++) {
        float4 av = a4[lane + j * 32];
        float4 bv = b4[lane + j * 32];
        float ox = av.x * (v[j].x - mean) * rinv + bv.x;
        float oy = av.y * (v[j].y - mean) * rinv + bv.y;
        float oz = av.z * (v[j].z - mean) * rinv + bv.z;
        float ow = av.w * (v[j].w - mean) * rinv + bv.w;
        long e = (long)row * DMODEL + (lane + j * 32) * 4;
        if (OB) {
            __nv_bfloat162 lo = __floats2bfloat162_rn(ox, oy);
            __nv_bfloat162 hi = __floats2bfloat162_rn(oz, ow);
            *(__nv_bfloat162*)(outb + e)     = lo;
            *(__nv_bfloat162*)(outb + e + 2) = hi;
        } else {
            *(float4*)(outf + e) = make_float4(ox, oy, oz, ow);
        }
    }
}

// ---------------- fused attention: QK^T + mask + softmax + PV -------------
// CTA: 128 q-rows, full 256 keys, one (b,h) per blockIdx.y. grid (2, 64).
#define ATT_NST 4
// dynamic smem layout (bytes):
//  QK phase:  As 0..40960 (4*128*40 bf16), Bs 40960..122880 (4*256*40 bf16)
//  PV phase:  P  0..67584 (128*264 bf16), V 67584..135168 (4*32*264 bf16),
//             pmax 135168..137216 (128*4 f32), psum 137216..139264
#define ATT_SMEM_BYTES 139264
#define ATT_P_ELOFF    0
#define ATT_V_ELOFF    33792
#define ATT_PMAX_BOFF  135168
#define ATT_PSUM_BOFF  137216

__global__ void __launch_bounds__(256)
attn_fused(const __nv_bfloat16* __restrict__ qkv,
           const int* __restrict__ attn_m,
           __nv_bfloat16* __restrict__ ob)
{
    extern __shared__ __align__(16) char smem_raw[];
    __nv_bfloat16* As = (__nv_bfloat16*)smem_raw;        // QK phase
    __nv_bfloat16* Bs = As + ATT_NST * 128 * 40;
    __nv_bfloat16* Ps = (__nv_bfloat16*)smem_raw + ATT_P_ELOFF;
    __nv_bfloat16* Vs = (__nv_bfloat16*)smem_raw + ATT_V_ELOFF;
    float* pmax = (float*)(smem_raw + ATT_PMAX_BOFF);    // [128][4]
    float* psum = (float*)(smem_raw + ATT_PSUM_BOFF);    // [128][4]
    __shared__ int msk[SS];

    const int z = blockIdx.y;            // b*8+h
    const int b = z >> 3, h = z & 7;
    const int m0 = blockIdx.x << 7;
    const long sQb = (long)SS * QKVN;
    const __nv_bfloat16* A = qkv + b * sQb + (long)h * DKH + (long)m0 * QKVN;
    const __nv_bfloat16* K = qkv + HD + b * sQb + (long)h * DKH;
    const __nv_bfloat16* V = qkv + 2 * HD + b * sQb + (long)h * DKH;

    const int tid  = threadIdx.x;
    const int wid  = tid >> 5;
    const int lane = tid & 31;
    const int mbase = (wid >> 2) * 64;
    const int nbase = (wid & 3) * 64;
    const int wn = wid & 3;
    const int lr  = ((lane >> 3) & 1) * 8 + (lane & 7);
    const int lc8 = (lane >> 4) * 8;
    const int lg = lane >> 2, lt = lane & 3;

    if (tid < SS) msk[tid] = attn_m[b * SS + tid];

    uint32_t sAs = (uint32_t)__cvta_generic_to_shared(As);
    uint32_t sBs = (uint32_t)__cvta_generic_to_shared(Bs);
    uint32_t sPs = (uint32_t)__cvta_generic_to_shared(Ps);
    uint32_t sVs = (uint32_t)__cvta_generic_to_shared(Vs);

    float acc[4][8][4];
    #pragma unroll
    for (int i = 0; i < 4; i++)
        #pragma unroll
        for (int j = 0; j < 8; j++)
            #pragma unroll
            for (int r = 0; r < 4; r++) acc[i][j][r] = 0.f;

    // ---------------- phase 1: S = q @ k^T ----------------
    auto stageQK = [&](int s, int kb) {
        #pragma unroll
        for (int t = 0; t < 2; t++) {
            int idx = tid + t * 256;
            int row = idx >> 2, ck = idx & 3;
            uint32_t d = sAs + 2u * ((s * 128 + row) * 40 + ck * 8);
            cpa16(d, A + (long)row * QKVN + kb + ck * 8);
        }
        #pragma unroll
        for (int t = 0; t < 4; t++) {
            int idx = tid + t * 256;
            int row = idx >> 2, ck = idx & 3;
            uint32_t d = sBs + 2u * ((s * 256 + row) * 40 + ck * 8);
            cpa16(d, K + (long)row * QKVN + kb + ck * 8);
        }
    };

    const int NIT = DKH / 32;     // 8
    stageQK(0, 0);  cp_commit();
    stageQK(1, 32); cp_commit();
    stageQK(2, 64); cp_commit();

    for (int it = 0; it < NIT; it++) {
        int s = it & 3;
        cp_wait<2>();
        __syncthreads();

        #pragma unroll
        for (int ks = 0; ks < 32; ks += 16) {
            uint32_t a[4][4], bf[8][2];
            #pragma unroll
            for (int i = 0; i < 4; i++) {
                uint32_t addr = sAs + 2u * ((s * 128 + mbase + i * 16 + lr) * 40 + ks + lc8);
                ldsm4(a[i][0], a[i][1], a[i][2], a[i][3], addr);
            }
            #pragma unroll
            for (int jb = 0; jb < 4; jb++) {
                uint32_t r0, r1, r2, r3;
                uint32_t addr = sBs + 2u * ((s * 256 + nbase + jb * 16 + lr) * 40 + ks + lc8);
                ldsm4(r0, r1, r2, r3, addr);
                bf[jb * 2 + 0][0] = r0; bf[jb * 2 + 0][1] = r2;
                bf[jb * 2 + 1][0] = r1; bf[jb * 2 + 1][1] = r3;
            }
            #pragma unroll
            for (int i = 0; i < 4; i++)
                #pragma unroll
                for (int j = 0; j < 8; j++)
                    mma_bf16(acc[i][j], a[i], bf[j]);
        }

        if (it + 3 < NIT) stageQK((it + 3) & 3, (it + 3) << 5);
        cp_commit();
    }
    cp_wait<0>();
    __syncthreads();    // QK staging dead; smem reusable

    // ---------------- kick V prefetch (independent of softmax) -------------
    // 32 rows x 256 cols per stage = 32 x 32 chunks of 8 bf16 (16B each)
    auto stageV = [&](int s, int k0) {
        #pragma unroll
        for (int t = 0; t < 4; t++) {
            int idx = tid + t * 256;
            int row = idx >> 5, c8 = idx & 31;
            uint32_t d = sVs + 2u * ((s * 32 + row) * 264 + c8 * 8);
            cpa16(d, V + (long)(k0 + row) * QKVN + c8 * 8);
        }
    };
    stageV(0, 0);  cp_commit();
    stageV(1, 32); cp_commit();
    stageV(2, 64); cp_commit();

    // ---------------- phase 2: softmax on accumulators ---------------------
    #pragma unroll
    for (int i = 0; i < 4; i++) {
        float m0v = -1e30f, m1v = -1e30f;
        #pragma unroll
        for (int j = 0; j < 8; j++) {
            int c0 = nbase + j * 8 + lt * 2;
            bool k0 = msk[c0] != 0, k1 = msk[c0 + 1] != 0;
            acc[i][j][0] = k0 ? -1e9f : acc[i][j][0] * 0.0625f;
            acc[i][j][1] = k1 ? -1e9f : acc[i][j][1] * 0.0625f;
            acc[i][j][2] = k0 ? -1e9f : acc[i][j][2] * 0.0625f;
            acc[i][j][3] = k1 ? -1e9f : acc[i][j][3] * 0.0625f;
            m0v = fmaxf(m0v, fmaxf(acc[i][j][0], acc[i][j][1]));
            m1v = fmaxf(m1v, fmaxf(acc[i][j][2], acc[i][j][3]));
        }
        m0v = fmaxf(m0v, __shfl_xor_sync(0xffffffff, m0v, 1));
        m0v = fmaxf(m0v, __shfl_xor_sync(0xffffffff, m0v, 2));
        m1v = fmaxf(m1v, __shfl_xor_sync(0xffffffff, m1v, 1));
        m1v = fmaxf(m1v, __shfl_xor_sync(0xffffffff, m1v, 2));
        if (lt == 0) {
            pmax[(mbase + i * 16 + lg) * 4 + wn]     = m0v;
            pmax[(mbase + i * 16 + 8 + lg) * 4 + wn] = m1v;
        }
    }
    __syncthreads();

    float rinv0[4], rinv1[4];
    #pragma unroll
    for (int i = 0; i < 4; i++) {
        int r0 = mbase + i * 16 + lg;
        const float* px0 = pmax + r0 * 4;
        const float* px1 = pmax + (r0 + 8) * 4;
        float g0 = fmaxf(fmaxf(px0[0], px0[1]), fmaxf(px0[2], px0[3]));
        float g1 = fmaxf(fmaxf(px1[0], px1[1]), fmaxf(px1[2], px1[3]));
        float s0 = 0.f, s1 = 0.f;
        #pragma unroll
        for (int j = 0; j < 8; j++) {
            acc[i][j][0] = expf(acc[i][j][0] - g0);
            acc[i][j][1] = expf(acc[i][j][1] - g0);
            acc[i][j][2] = expf(acc[i][j][2] - g1);
            acc[i][j][3] = expf(acc[i][j][3] - g1);
            s0 += acc[i][j][0] + acc[i][j][1];
            s1 += acc[i][j][2] + acc[i][j][3];
        }
        s0 += __shfl_xor_sync(0xffffffff, s0, 1);
        s0 += __shfl_xor_sync(0xffffffff, s0, 2);
        s1 += __shfl_xor_sync(0xffffffff, s1, 1);
        s1 += __shfl_xor_sync(0xffffffff, s1, 2);
        if (lt == 0) {
            psum[r0 * 4 + wn]       = s0;
            psum[(r0 + 8) * 4 + wn] = s1;
        }
    }
    __syncthreads();

    #pragma unroll
    for (int i = 0; i < 4; i++) {
        int r0 = mbase + i * 16 + lg;
        const float* ps0 = psum + r0 * 4;
        const float* ps1 = psum + (r0 + 8) * 4;
        rinv0[i] = 1.0f / (ps0[0] + ps0[1] + ps0[2] + ps0[3]);
        rinv1[i] = 1.0f / (ps1[0] + ps1[1] + ps1[2] + ps1[3]);
        #pragma unroll
        for (int j = 0; j < 8; j++) {
            int c0 = nbase + j * 8 + lt * 2;
            *(__nv_bfloat162*)(Ps + (r0 * 264 + c0)) =
                __floats2bfloat162_rn(acc[i][j][0] * rinv0[i], acc[i][j][1] * rinv0[i]);
            *(__nv_bfloat162*)(Ps + ((r0 + 8) * 264 + c0)) =
                __floats2bfloat162_rn(acc[i][j][2] * rinv1[i], acc[i][j][3] * rinv1[i]);
        }
    }

    // ---------------- phase 3: O = P @ V ----------------
    #pragma unroll
    for (int i = 0; i < 4; i++)
        #pragma unroll
        for (int j = 0; j < 8; j++)
            #pragma unroll
            for (int r = 0; r < 4; r++) acc[i][j][r] = 0.f;

    for (int it = 0; it < 8; it++) {          // K = 256 keys, 32 per iter
        int s = it & 3;
        cp_wait<2>();
        __syncthreads();                       // also publishes Ps on iter 0

        #pragma unroll
        for (int ks = 0; ks < 32; ks += 16) {
            int kg = it * 32 + ks;
            uint32_t a[4][4], bf[8][2];
            #pragma unroll
            for (int i = 0; i < 4; i++) {
                uint32_t addr = sPs + 2u * ((mbase + i * 16 + lr) * 264 + kg + lc8);
                ldsm4(a[i][0], a[i][1], a[i][2], a[i][3], addr);
            }
            #pragma unroll
            for (int jb = 0; jb < 4; jb++) {
                uint32_t r0, r1, r2, r3;
                uint32_t addr = sVs + 2u * ((s * 32 + ks + lr) * 264 + nbase + jb * 16 + lc8);
                ldsm4t(r0, r1, r2, r3, addr);
                bf[jb * 2 + 0][0] = r0; bf[jb * 2 + 0][1] = r1;
                bf[jb * 2 + 1][0] = r2; bf[jb * 2 + 1][1] = r3;
            }
            #pragma unroll
            for (int i = 0; i < 4; i++)
                #pragma unroll
                for (int j = 0; j < 8; j++)
                    mma_bf16(acc[i][j], a[i], bf[j]);
        }

        if (it + 3 < 8) stageV((it + 3) & 3, (it + 3) << 5);
        cp_commit();
    }

    // epilogue: O -> g_ob [b*SS + m][h*DKH + n] bf16
    #pragma unroll
    for (int i = 0; i < 4; i++) {
        int r0 = mbase + i * 16 + lg;
        long base0 = (long)(b * SS + m0 + r0) * HD + h * DKH;
        long base1 = (long)(b * SS + m0 + r0 + 8) * HD + h * DKH;
        #pragma unroll
        for (int j = 0; j < 8; j++) {
            int c0 = nbase + j * 8 + lt * 2;
            *(__nv_bfloat162*)(ob + base0 + c0) =
                __floats2bfloat162_rn(acc[i][j][0], acc[i][j][1]);
            *(__nv_bfloat162*)(ob + base1 + c0) =
                __floats2bfloat162_rn(acc[i][j][2], acc[i][j][3]);
        }
    }
}

// ---------------- bf16 tensor-core GEMM, 4-stage cp.async pipeline --------
#define NSTAGE 4
template<int BM, bool TB>
struct SmemCfg {
    static constexpr int BROWS = TB ? 128 : 32;
    static constexpr int BCOLS = TB ? 40 : 136;
    static constexpr int A_ELEMS = NSTAGE * BM * 40;
    static constexpr int B_ELEMS = NSTAGE * BROWS * BCOLS;
    static constexpr int BYTES = (A_ELEMS + B_ELEMS) * 2;
};

template<int BM, bool TB, bool RELU, bool RES, bool OUTBF>
__global__ void __launch_bounds__(256)
gemm_bf(const __nv_bfloat16* __restrict__ A, const __nv_bfloat16* __restrict__ B,
        const float* __restrict__ bias, const float* __restrict__ res,
        float* __restrict__ Cf, __nv_bfloat16* __restrict__ Cb,
        int K, int lda, int ldb, int ldc,
        long sAb, long sAh, long sBb, long sBh, long sCb, long sCh)
{
    constexpr int IT = BM / 32;

    extern __shared__ __align__(16) char smem_raw[];
    __nv_bfloat16* As = (__nv_bfloat16*)smem_raw;
    __nv_bfloat16* Bs = As + SmemCfg<BM,TB>::A_ELEMS;

    int z = blockIdx.z;
    int bb = z >> 3, hh = z & 7;
    A += bb * sAb + hh * sAh;
    B += bb * sBb + hh * sBh;
    if (RES) res += bb * sCb + hh * sCh;
    long cbase = bb * sCb + hh * sCh;

    const int m0 = blockIdx.y * BM, n0 = blockIdx.x << 7;
    const int tid  = threadIdx.x;
    const int wid  = tid >> 5;
    const int lane = tid & 31;
    const int mbase = (wid >> 2) * (BM / 2);
    const int nbase = (wid & 3) * 32;
    const int lr  = ((lane >> 3) & 1) * 8 + (lane & 7);
    const int lc8 = (lane >> 4) * 8;

    uint32_t sAs = (uint32_t)__cvta_generic_to_shared(As);
    uint32_t sBs = (uint32_t)__cvta_generic_to_shared(Bs);

    float acc[IT][4][4];
    #pragma unroll
    for (int i = 0; i < IT; i++)
        #pragma unroll
        for (int j = 0; j < 4; j++)
            #pragma unroll
            for (int r = 0; r < 4; r++) acc[i][j][r] = 0.f;

    auto stage = [&](int s, int kb) {
        #pragma unroll
        for (int t = 0; t < BM / 64; t++) {
            int idx = tid + t * 256;
            int row = idx >> 2, ck = idx & 3;
            uint32_t d = sAs + 2u * ((s * BM + row) * 40 + ck * 8);
            cpa16(d, A + (long)(m0 + row) * lda + kb + ck * 8);
        }
        if (!TB) {
            #pragma unroll
            for (int t = 0; t < 2; t++) {
                int idx = tid + t * 256;
                int row = idx >> 4, ck = idx & 15;
                uint32_t d = sBs + 2u * ((s * 32 + row) * 136 + ck * 8);
                cpa16(d, B + (long)(kb + row) * ldb + n0 + ck * 8);
            }
        } else {
            #pragma unroll
            for (int t = 0; t < 2; t++) {
                int idx = tid + t * 256;
                int row = idx >> 2, ck = idx & 3;
                uint32_t d = sBs + 2u * ((s * 128 + row) * 40 + ck * 8);
                cpa16(d, B + (long)(n0 + row) * ldb + kb + ck * 8);
            }
        }
    };

    const int NIT = K >> 5;
    stage(0, 0);  cp_commit();
    stage(1, 32); cp_commit();
    stage(2, 64); cp_commit();

    for (int it = 0; it < NIT; it++) {
        int s = it & 3;
        cp_wait<2>();
        __syncthreads();

        #pragma unroll
        for (int ks = 0; ks < 32; ks += 16) {
            uint32_t a[IT][4], bf[4][2];
            #pragma unroll
            for (int i = 0; i < IT; i++) {
                uint32_t addr = sAs + 2u * ((s * BM + mbase + i * 16 + lr) * 40 + ks + lc8);
                ldsm4(a[i][0], a[i][1], a[i][2], a[i][3], addr);
            }
            #pragma unroll
            for (int jb = 0; jb < 2; jb++) {
                uint32_t r0, r1, r2, r3;
                if (!TB) {
                    uint32_t addr = sBs + 2u * ((s * 32 + ks + lr) * 136 + nbase + jb * 16 + lc8);
                    ldsm4t(r0, r1, r2, r3, addr);
                    bf[jb * 2 + 0][0] = r0; bf[jb * 2 + 0][1] = r1;
                    bf[jb * 2 + 1][0] = r2; bf[jb * 2 + 1][1] = r3;
                } else {
                    uint32_t addr = sBs + 2u * ((s * 128 + nbase + jb * 16 + lr) * 40 + ks + lc8);
                    ldsm4(r0, r1, r2, r3, addr);
                    bf[jb * 2 + 0][0] = r0; bf[jb * 2 + 0][1] = r2;
                    bf[jb * 2 + 1][0] = r1; bf[jb * 2 + 1][1] = r3;
                }
            }
            #pragma unroll
            for (int i = 0; i < IT; i++)
                #pragma unroll
                for (int j = 0; j < 4; j++)
                    mma_bf16(acc[i][j], a[i], bf[j]);
        }

        if (it + 3 < NIT) stage((it + 3) & 3, (it + 3) << 5);
        cp_commit();
    }

    #pragma unroll
    for (int i = 0; i < IT; i++) {
        int r0 = m0 + mbase + i * 16 + (lane >> 2);
        #pragma unroll
        for (int j = 0; j < 4; j++) {
            int c0 = n0 + nbase + j * 8 + (lane & 3) * 2;
            float b0 = 0.f, b1 = 0.f;
            if (bias) { b0 = bias[c0]; b1 = bias[c0 + 1]; }
            float v00 = acc[i][j][0] + b0, v01 = acc[i][j][1] + b1;
            float v10 = acc[i][j][2] + b0, v11 = acc[i][j][3] + b1;
            if (RELU) {
                v00 = fmaxf(v00, 0.f); v01 = fmaxf(v01, 0.f);
                v10 = fmaxf(v10, 0.f); v11 = fmaxf(v11, 0.f);
            }
            if (RES) {
                v00 += res[(long)r0 * ldc + c0];
                v01 += res[(long)r0 * ldc + c0 + 1];
                v10 += res[(long)(r0 + 8) * ldc + c0];
                v11 += res[(long)(r0 + 8) * ldc + c0 + 1];
            }
            if (OUTBF) {
                *(__nv_bfloat162*)(Cb + cbase + (long)r0 * ldc + c0) =
                    __floats2bfloat162_rn(v00, v01);
                *(__nv_bfloat162*)(Cb + cbase + (long)(r0 + 8) * ldc + c0) =
                    __floats2bfloat162_rn(v10, v11);
            } else {
                *(float2*)(Cf + cbase + (long)r0 * ldc + c0)       = make_float2(v00, v01);
                *(float2*)(Cf + cbase + (long)(r0 + 8) * ldc + c0) = make_float2(v10, v11);
            }
        }
    }
}

// ---------------------------------------------------------------------------
extern "C" void kernel_launch(void* const* d_in, const int* in_sizes, int n_in,
                              void* d_out, int out_size)
{
    const float* data    = (const float*)d_in[0];
    const int*   attn_m  = (const int*)  d_in[1];
    const int*   view    = (const int*)  d_in[2];
    const float* seg_emb = (const float*)d_in[3];
    const float* Wq = (const float*)d_in[4];
    const float* bq = (const float*)d_in[5];
    const float* Wk = (const float*)d_in[6];
    const float* bk = (const float*)d_in[7];
    const float* Wv = (const float*)d_in[8];
    const float* bv = (const float*)d_in[9];
    const float* Wo = (const float*)d_in[10];
    const float* bo = (const float*)d_in[11];
    const float* W1 = (const float*)d_in[12];
    const float* b1 = (const float*)d_in[13];
    const float* W2 = (const float*)d_in[14];
    const float* b2 = (const float*)d_in[15];
    const float* alpha1 = (const float*)d_in[16];
    const float* bias1  = (const float*)d_in[17];
    const float* alpha2 = (const float*)d_in[18];
    const float* bias2  = (const float*)d_in[19];
    const float* alpha_f = (const float*)d_in[20];
    const float* bias_f  = (const float*)d_in[21];
    float* out = (float*)d_out;

    float *x;
    __nv_bfloat16 *x2b, *qkv, *ob, *fb;
    __nv_bfloat16 *wqkv, *wo, *w1, *w2;
    float *bqkv;
    cudaGetSymbolAddress((void**)&x,    g_x);
    cudaGetSymbolAddress((void**)&x2b,  g_x2b);
    cudaGetSymbolAddress((void**)&qkv,  g_qkv);
    cudaGetSymbolAddress((void**)&ob,   g_ob);
    cudaGetSymbolAddress((void**)&fb,   g_fb);
    cudaGetSymbolAddress((void**)&wqkv, g_wqkv);
    cudaGetSymbolAddress((void**)&bqkv, g_bqkv);
    cudaGetSymbolAddress((void**)&wo,   g_wo);
    cudaGetSymbolAddress((void**)&w1,   g_w1);
    cudaGetSymbolAddress((void**)&w2,   g_w2);

    constexpr int SM_NN128 = SmemCfg<128,false>::BYTES;   // 75776
    constexpr int SM_NN64  = SmemCfg<64, false>::BYTES;   // 55296
    cudaFuncSetAttribute(gemm_bf<128,false,false,false,true>,
        cudaFuncAttributeMaxDynamicSharedMemorySize, SM_NN128);
    cudaFuncSetAttribute(gemm_bf<128,false,true,false,true>,
        cudaFuncAttributeMaxDynamicSharedMemorySize, SM_NN128);
    cudaFuncSetAttribute(gemm_bf<64,false,false,true,false>,
        cudaFuncAttributeMaxDynamicSharedMemorySize, SM_NN64);
    cudaFuncSetAttribute(attn_fused,
        cudaFuncAttributeMaxDynamicSharedMemorySize, ATT_SMEM_BYTES);

    cvt_weights<<<(6 * (WSZ / 4)) / 256, 256>>>(Wq, Wk, Wv, Wo, W1, W2);
    cvt_bias<<<(LNUM * QKVN + 255) / 256, 256>>>(bq, bk, bv);
    embed_kernel<<<(TOK * DMODEL + 255) / 256, 256>>>(data, seg_emb, view, x);

    for (int i = 0; i < LNUM; i++) {
        layernorm_kernel<true><<<TOK / 8, 256>>>(x, alpha1 + i * DMODEL, bias1 + i * DMODEL,
                                                 nullptr, x2b);

        // fused QKV: [2048,512] @ [512,6144]
        dim3 gp(QKVN / 128, TOK / 128, 1);
        gemm_bf<128,false,false,false,true><<<gp, 256, SM_NN128>>>(
            x2b, wqkv + (long)i * DMODEL * QKVN, bqkv + (long)i * QKVN,
            nullptr, nullptr, qkv, DMODEL, DMODEL, QKVN, QKVN, 0,0,0,0,0,0);

        // fused attention: scores + softmax + PV -> g_ob
        dim3 gs(SS / 128, BB * HEADS);
        attn_fused<<<gs, 256, ATT_SMEM_BYTES>>>(qkv, attn_m, ob);

        // x = x + o @ Wo + bo
        dim3 go(DMODEL / 128, TOK / 64, 1);
        gemm_bf<64,false,false,true,false><<<go, 256, SM_NN64>>>(
            ob, wo + (long)i * HD * DMODEL, bo + (long)i * DMODEL,
            x, x, nullptr, HD, HD, DMODEL, DMODEL, 0,0,0,0,0,0);

        layernorm_kernel<true><<<TOK / 8, 256>>>(x, alpha2 + i * DMODEL, bias2 + i * DMODEL,
                                                 nullptr, x2b);

        // ff = relu(x2 @ W1 + b1)
        dim3 gf(DFFN / 128, TOK / 128, 1);
        gemm_bf<128,false,true,false,true><<<gf, 256, SM_NN128>>>(
            x2b, w1 + (long)i * DMODEL * DFFN, b1 + (long)i * DFFN,
            nullptr, nullptr, fb, DMODEL, DMODEL, DFFN, DFFN, 0,0,0,0,0,0);

        // x = x + ff @ W2 + b2
        gemm_bf<64,false,false,true,false><<<go, 256, SM_NN64>>>(
            fb, w2 + (long)i * DFFN * DMODEL, b2 + (long)i * DMODEL,
            x, x, nullptr, DFFN, DFFN, DMODEL, DMODEL, 0,0,0,0,0,0);
    }

    layernorm_kernel<false><<<TOK / 8, 256>>>(x, alpha_f, bias_f, out, nullptr);
}

// round 10
// speedup vs baseline: 9.0417x; 1.0475x over previous
#include <cuda_runtime.h>
#include <cuda_bf16.h>
#include <math.h>
#include <stdint.h>

#define LNUM 4
#define DMODEL 512
#define HEADS 8
#define DKH 256
#define DFFN 2048
#define BB 8
#define SS 256
#define HD (HEADS*DKH)          // 2048
#define TOK (BB*SS)             // 2048
#define QKVN (3*HD)             // 6144
#define EPS 1e-6f

// ---------------- scratch (device globals; no allocations) ----------------
__device__ float g_x [TOK*DMODEL];          // fp32 residual stream

__device__ __nv_bfloat16 g_x2b [TOK*DMODEL];
__device__ __nv_bfloat16 g_qkv [TOK*QKVN];  // packed q|k|v
__device__ __nv_bfloat16 g_ob  [TOK*HD];
__device__ __nv_bfloat16 g_fb  [TOK*DFFN];
// bf16 weights
#define WSZ 4194304                          // 4*512*2048
__device__ __nv_bfloat16 g_wqkv[LNUM*DMODEL*QKVN];   // packed per-layer [512][6144]
__device__ float         g_bqkv[LNUM*QKVN];
__device__ __nv_bfloat16 g_wo[WSZ];
__device__ __nv_bfloat16 g_w1[WSZ];
__device__ __nv_bfloat16 g_w2[WSZ];

// ---------------- PTX helpers ---------------------------------------------
__device__ __forceinline__ void cpa16(uint32_t dst, const void* src) {
    asm volatile("cp.async.cg.shared.global [%0], [%1], 16;" :: "r"(dst), "l"(src) : "memory");
}
__device__ __forceinline__ void cp_commit() {
    asm volatile("cp.async.commit_group;" ::: "memory");
}
template<int N>
__device__ __forceinline__ void cp_wait() {
    asm volatile("cp.async.wait_group %0;" :: "n"(N) : "memory");
}
__device__ __forceinline__ void ldsm4(uint32_t& r0, uint32_t& r1, uint32_t& r2, uint32_t& r3, uint32_t a) {
    asm volatile("ldmatrix.sync.aligned.m8n8.x4.shared.b16 {%0,%1,%2,%3}, [%4];"
                 : "=r"(r0), "=r"(r1), "=r"(r2), "=r"(r3) : "r"(a));
}
__device__ __forceinline__ void ldsm4t(uint32_t& r0, uint32_t& r1, uint32_t& r2, uint32_t& r3, uint32_t a) {
    asm volatile("ldmatrix.sync.aligned.m8n8.x4.trans.shared.b16 {%0,%1,%2,%3}, [%4];"
                 : "=r"(r0), "=r"(r1), "=r"(r2), "=r"(r3) : "r"(a));
}
__device__ __forceinline__ void mma_bf16(float* d, const uint32_t* a, const uint32_t* b) {
    asm volatile("mma.sync.aligned.m16n8k16.row.col.f32.bf16.bf16.f32 "
                 "{%0,%1,%2,%3}, {%4,%5,%6,%7}, {%8,%9}, {%0,%1,%2,%3};"
                 : "+f"(d[0]), "+f"(d[1]), "+f"(d[2]), "+f"(d[3])
                 : "r"(a[0]), "r"(a[1]), "r"(a[2]), "r"(a[3]), "r"(b[0]), "r"(b[1]));
}

// ---------------- weight fp32 -> bf16 (once per launch) -------------------
__global__ void cvt_weights(const float* __restrict__ wq, const float* __restrict__ wk,
                            const float* __restrict__ wv, const float* __restrict__ wo,
                            const float* __restrict__ w1, const float* __restrict__ w2)
{
    long i4 = (long)blockIdx.x * blockDim.x + threadIdx.x;
    int which = (int)(i4 >> 20);
    long off = (i4 & ((1L << 20) - 1)) << 2;
    const float* s;
    __nv_bfloat16* d;
    long doff = off;
    if (which < 3) {
        s = (which == 0) ? wq : (which == 1) ? wk : wv;
        long l   = off / ((long)DMODEL * HD);
        long win = off - l * (long)DMODEL * HD;
        long row = win / HD;
        long col = win - row * HD;
        d = g_wqkv;
        doff = l * (long)DMODEL * QKVN + row * QKVN + which * HD + col;
    } else {
        s = (which == 3) ? wo : (which == 4) ? w1 : w2;
        d = (which == 3) ? g_wo : (which == 4) ? g_w1 : g_w2;
    }
    float4 v = *(const float4*)(s + off);
    *(__nv_bfloat162*)(d + doff)     = __floats2bfloat162_rn(v.x, v.y);
    *(__nv_bfloat162*)(d + doff + 2) = __floats2bfloat162_rn(v.z, v.w);
}

__global__ void cvt_bias(const float* __restrict__ bq, const float* __restrict__ bk,
                         const float* __restrict__ bv)
{
    int idx = blockIdx.x * blockDim.x + threadIdx.x;
    if (idx >= LNUM * QKVN) return;
    int l = idx / QKVN;
    int c = idx - l * QKVN;
    int which = c >> 11;
    int col = c & (HD - 1);
    const float* s = (which == 0) ? bq : (which == 1) ? bk : bv;
    g_bqkv[idx] = s[l * HD + col];
}

// ---------------- embed ----------------------------------------------------
__global__ void embed_kernel(const float* __restrict__ data,
                             const float* __restrict__ seg_emb,
                             const int* __restrict__ view,
                             float* __restrict__ x)
{
    int idx = blockIdx.x * blockDim.x + threadIdx.x;
    if (idx >= TOK * DMODEL) return;
    int c = idx & (DMODEL - 1);
    int s = (idx >> 9) & (SS - 1);
    float inv = exp2f(-(float)c * (1.0f / 32.0f));
    float arg = (float)s * inv;
    float pe  = (c & 1) ? cosf(arg) : sinf(arg);
    int seg_off = view[0] * SS * DMODEL + c;
    x[idx] = data[idx] * sqrtf((float)DMODEL) + pe + seg_emb[seg_off];
}

// ---------------- layernorm: warp handles 2 rows (MLP=8) ------------------
// grid = TOK/16, 256 threads = 8 warps x 2 rows.
template<bool OB>
__global__ void layernorm_kernel(const float* __restrict__ x,
                                 const float* __restrict__ alpha,
                                 const float* __restrict__ beta,
                                 float* __restrict__ outf,
                                 __nv_bfloat16* __restrict__ outb)
{
    const int wid = threadIdx.x >> 5, lane = threadIdx.x & 31;
    const int row0 = blockIdx.x * 16 + wid * 2;

    float4 v[2][4];
    float s[2] = {0.f, 0.f}, sq[2] = {0.f, 0.f};
    #pragma unroll
    for (int r = 0; r < 2; r++) {
        const float4* p4 = (const float4*)(x + (long)(row0 + r) * DMODEL);
        #pragma unroll
        for (int j = 0; j < 4; j++) {
            v[r][j] = p4[lane + j * 32];
            s[r]  += v[r][j].x + v[r][j].y + v[r][j].z + v[r][j].w;
            sq[r] += v[r][j].x * v[r][j].x + v[r][j].y * v[r][j].y
                   + v[r][j].z * v[r][j].z + v[r][j].w * v[r][j].w;
        }
    }
    #pragma unroll
    for (int off = 16; off > 0; off >>= 1) {
        s[0]  += __shfl_xor_sync(0xffffffff, s[0],  off);
        sq[0] += __shfl_xor_sync(0xffffffff, sq[0], off);
        s[1]  += __shfl_xor_sync(0xffffffff, s[1],  off);
        sq[1] += __shfl_xor_sync(0xffffffff, sq[1], off);
    }

    const float4* a4 = (const float4*)alpha;
    const float4* b4 = (const float4*)beta;
    #pragma unroll
    for (int r = 0; r < 2; r++) {
        float mean = s[r] * (1.0f / DMODEL);
        float var  = (sq[r] - (float)DMODEL * mean * mean) * (1.0f / (DMODEL - 1));
        var = fmaxf(var, 0.f);
        float rinv = 1.0f / (sqrtf(var) + EPS);
        #pragma unroll
        for (int j = 0; j < 4; j++) {
            float4 av = a4[lane + j * 32];
            float4 bv = b4[lane + j * 32];
            float ox = av.x * (v[r][j].x - mean) * rinv + bv.x;
            float oy = av.y * (v[r][j].y - mean) * rinv + bv.y;
            float oz = av.z * (v[r][j].z - mean) * rinv + bv.z;
            float ow = av.w * (v[r][j].w - mean) * rinv + bv.w;
            long e = (long)(row0 + r) * DMODEL + (lane + j * 32) * 4;
            if (OB) {
                *(__nv_bfloat162*)(outb + e)     = __floats2bfloat162_rn(ox, oy);
                *(__nv_bfloat162*)(outb + e + 2) = __floats2bfloat162_rn(oz, ow);
            } else {
                *(float4*)(outf + e) = make_float4(ox, oy, oz, ow);
            }
        }
    }
}

// ---------------- fused attention: QK^T + mask + softmax + PV -------------
// (unchanged from R9 — BK=32, 4 stages)
#define ATT_NST 4
#define ATT_SMEM_BYTES 139264
#define ATT_P_ELOFF    0
#define ATT_V_ELOFF    33792
#define ATT_PMAX_BOFF  135168
#define ATT_PSUM_BOFF  137216

__global__ void __launch_bounds__(256)
attn_fused(const __nv_bfloat16* __restrict__ qkv,
           const int* __restrict__ attn_m,
           __nv_bfloat16* __restrict__ ob)
{
    extern __shared__ __align__(16) char smem_raw[];
    __nv_bfloat16* As = (__nv_bfloat16*)smem_raw;
    __nv_bfloat16* Bs = As + ATT_NST * 128 * 40;
    __nv_bfloat16* Ps = (__nv_bfloat16*)smem_raw + ATT_P_ELOFF;
    __nv_bfloat16* Vs = (__nv_bfloat16*)smem_raw + ATT_V_ELOFF;
    float* pmax = (float*)(smem_raw + ATT_PMAX_BOFF);
    float* psum = (float*)(smem_raw + ATT_PSUM_BOFF);
    __shared__ int msk[SS];

    const int z = blockIdx.y;
    const int b = z >> 3, h = z & 7;
    const int m0 = blockIdx.x << 7;
    const long sQb = (long)SS * QKVN;
    const __nv_bfloat16* A = qkv + b * sQb + (long)h * DKH + (long)m0 * QKVN;
    const __nv_bfloat16* K = qkv + HD + b * sQb + (long)h * DKH;
    const __nv_bfloat16* V = qkv + 2 * HD + b * sQb + (long)h * DKH;

    const int tid  = threadIdx.x;
    const int wid  = tid >> 5;
    const int lane = tid & 31;
    const int mbase = (wid >> 2) * 64;
    const int nbase = (wid & 3) * 64;
    const int wn = wid & 3;
    const int lr  = ((lane >> 3) & 1) * 8 + (lane & 7);
    const int lc8 = (lane >> 4) * 8;
    const int lg = lane >> 2, lt = lane & 3;

    if (tid < SS) msk[tid] = attn_m[b * SS + tid];

    uint32_t sAs = (uint32_t)__cvta_generic_to_shared(As);
    uint32_t sBs = (uint32_t)__cvta_generic_to_shared(Bs);
    uint32_t sPs = (uint32_t)__cvta_generic_to_shared(Ps);
    uint32_t sVs = (uint32_t)__cvta_generic_to_shared(Vs);

    float acc[4][8][4];
    #pragma unroll
    for (int i = 0; i < 4; i++)
        #pragma unroll
        for (int j = 0; j < 8; j++)
            #pragma unroll
            for (int r = 0; r < 4; r++) acc[i][j][r] = 0.f;

    auto stageQK = [&](int s, int kb) {
        #pragma unroll
        for (int t = 0; t < 2; t++) {
            int idx = tid + t * 256;
            int row = idx >> 2, ck = idx & 3;
            uint32_t d = sAs + 2u * ((s * 128 + row) * 40 + ck * 8);
            cpa16(d, A + (long)row * QKVN + kb + ck * 8);
        }
        #pragma unroll
        for (int t = 0; t < 4; t++) {
            int idx = tid + t * 256;
            int row = idx >> 2, ck = idx & 3;
            uint32_t d = sBs + 2u * ((s * 256 + row) * 40 + ck * 8);
            cpa16(d, K + (long)row * QKVN + kb + ck * 8);
        }
    };

    const int NIT = DKH / 32;     // 8
    stageQK(0, 0);  cp_commit();
    stageQK(1, 32); cp_commit();
    stageQK(2, 64); cp_commit();

    for (int it = 0; it < NIT; it++) {
        int s = it & 3;
        cp_wait<2>();
        __syncthreads();

        #pragma unroll
        for (int ks = 0; ks < 32; ks += 16) {
            uint32_t a[4][4], bf[8][2];
            #pragma unroll
            for (int i = 0; i < 4; i++) {
                uint32_t addr = sAs + 2u * ((s * 128 + mbase + i * 16 + lr) * 40 + ks + lc8);
                ldsm4(a[i][0], a[i][1], a[i][2], a[i][3], addr);
            }
            #pragma unroll
            for (int jb = 0; jb < 4; jb++) {
                uint32_t r0, r1, r2, r3;
                uint32_t addr = sBs + 2u * ((s * 256 + nbase + jb * 16 + lr) * 40 + ks + lc8);
                ldsm4(r0, r1, r2, r3, addr);
                bf[jb * 2 + 0][0] = r0; bf[jb * 2 + 0][1] = r2;
                bf[jb * 2 + 1][0] = r1; bf[jb * 2 + 1][1] = r3;
            }
            #pragma unroll
            for (int i = 0; i < 4; i++)
                #pragma unroll
                for (int j = 0; j < 8; j++)
                    mma_bf16(acc[i][j], a[i], bf[j]);
        }

        if (it + 3 < NIT) stageQK((it + 3) & 3, (it + 3) << 5);
        cp_commit();
    }
    cp_wait<0>();
    __syncthreads();

    auto stageV = [&](int s, int k0) {
        #pragma unroll
        for (int t = 0; t < 4; t++) {
            int idx = tid + t * 256;
            int row = idx >> 5, c8 = idx & 31;
            uint32_t d = sVs + 2u * ((s * 32 + row) * 264 + c8 * 8);
            cpa16(d, V + (long)(k0 + row) * QKVN + c8 * 8);
        }
    };
    stageV(0, 0);  cp_commit();
    stageV(1, 32); cp_commit();
    stageV(2, 64); cp_commit();

    #pragma unroll
    for (int i = 0; i < 4; i++) {
        float m0v = -1e30f, m1v = -1e30f;
        #pragma unroll
        for (int j = 0; j < 8; j++) {
            int c0 = nbase + j * 8 + lt * 2;
            bool k0 = msk[c0] != 0, k1 = msk[c0 + 1] != 0;
            acc[i][j][0] = k0 ? -1e9f : acc[i][j][0] * 0.0625f;
            acc[i][j][1] = k1 ? -1e9f : acc[i][j][1] * 0.0625f;
            acc[i][j][2] = k0 ? -1e9f : acc[i][j][2] * 0.0625f;
            acc[i][j][3] = k1 ? -1e9f : acc[i][j][3] * 0.0625f;
            m0v = fmaxf(m0v, fmaxf(acc[i][j][0], acc[i][j][1]));
            m1v = fmaxf(m1v, fmaxf(acc[i][j][2], acc[i][j][3]));
        }
        m0v = fmaxf(m0v, __shfl_xor_sync(0xffffffff, m0v, 1));
        m0v = fmaxf(m0v, __shfl_xor_sync(0xffffffff, m0v, 2));
        m1v = fmaxf(m1v, __shfl_xor_sync(0xffffffff, m1v, 1));
        m1v = fmaxf(m1v, __shfl_xor_sync(0xffffffff, m1v, 2));
        if (lt == 0) {
            pmax[(mbase + i * 16 + lg) * 4 + wn]     = m0v;
            pmax[(mbase + i * 16 + 8 + lg) * 4 + wn] = m1v;
        }
    }
    __syncthreads();

    float rinv0[4], rinv1[4];
    #pragma unroll
    for (int i = 0; i < 4; i++) {
        int r0 = mbase + i * 16 + lg;
        const float* px0 = pmax + r0 * 4;
        const float* px1 = pmax + (r0 + 8) * 4;
        float g0 = fmaxf(fmaxf(px0[0], px0[1]), fmaxf(px0[2], px0[3]));
        float g1 = fmaxf(fmaxf(px1[0], px1[1]), fmaxf(px1[2], px1[3]));
        float s0 = 0.f, s1 = 0.f;
        #pragma unroll
        for (int j = 0; j < 8; j++) {
            acc[i][j][0] = expf(acc[i][j][0] - g0);
            acc[i][j][1] = expf(acc[i][j][1] - g0);
            acc[i][j][2] = expf(acc[i][j][2] - g1);
            acc[i][j][3] = expf(acc[i][j][3] - g1);
            s0 += acc[i][j][0] + acc[i][j][1];
            s1 += acc[i][j][2] + acc[i][j][3];
        }
        s0 += __shfl_xor_sync(0xffffffff, s0, 1);
        s0 += __shfl_xor_sync(0xffffffff, s0, 2);
        s1 += __shfl_xor_sync(0xffffffff, s1, 1);
        s1 += __shfl_xor_sync(0xffffffff, s1, 2);
        if (lt == 0) {
            psum[r0 * 4 + wn]       = s0;
            psum[(r0 + 8) * 4 + wn] = s1;
        }
    }
    __syncthreads();

    #pragma unroll
    for (int i = 0; i < 4; i++) {
        int r0 = mbase + i * 16 + lg;
        const float* ps0 = psum + r0 * 4;
        const float* ps1 = psum + (r0 + 8) * 4;
        rinv0[i] = 1.0f / (ps0[0] + ps0[1] + ps0[2] + ps0[3]);
        rinv1[i] = 1.0f / (ps1[0] + ps1[1] + ps1[2] + ps1[3]);
        #pragma unroll
        for (int j = 0; j < 8; j++) {
            int c0 = nbase + j * 8 + lt * 2;
            *(__nv_bfloat162*)(Ps + (r0 * 264 + c0)) =
                __floats2bfloat162_rn(acc[i][j][0] * rinv0[i], acc[i][j][1] * rinv0[i]);
            *(__nv_bfloat162*)(Ps + ((r0 + 8) * 264 + c0)) =
                __floats2bfloat162_rn(acc[i][j][2] * rinv1[i], acc[i][j][3] * rinv1[i]);
        }
    }

    #pragma unroll
    for (int i = 0; i < 4; i++)
        #pragma unroll
        for (int j = 0; j < 8; j++)
            #pragma unroll
            for (int r = 0; r < 4; r++) acc[i][j][r] = 0.f;

    for (int it = 0; it < 8; it++) {
        int s = it & 3;
        cp_wait<2>();
        __syncthreads();

        #pragma unroll
        for (int ks = 0; ks < 32; ks += 16) {
            int kg = it * 32 + ks;
            uint32_t a[4][4], bf[8][2];
            #pragma unroll
            for (int i = 0; i < 4; i++) {
                uint32_t addr = sPs + 2u * ((mbase + i * 16 + lr) * 264 + kg + lc8);
                ldsm4(a[i][0], a[i][1], a[i][2], a[i][3], addr);
            }
            #pragma unroll
            for (int jb = 0; jb < 4; jb++) {
                uint32_t r0, r1, r2, r3;
                uint32_t addr = sVs + 2u * ((s * 32 + ks + lr) * 264 + nbase + jb * 16 + lc8);
                ldsm4t(r0, r1, r2, r3, addr);
                bf[jb * 2 + 0][0] = r0; bf[jb * 2 + 0][1] = r1;
                bf[jb * 2 + 1][0] = r2; bf[jb * 2 + 1][1] = r3;
            }
            #pragma unroll
            for (int i = 0; i < 4; i++)
                #pragma unroll
                for (int j = 0; j < 8; j++)
                    mma_bf16(acc[i][j], a[i], bf[j]);
        }

        if (it + 3 < 8) stageV((it + 3) & 3, (it + 3) << 5);
        cp_commit();
    }

    #pragma unroll
    for (int i = 0; i < 4; i++) {
        int r0 = mbase + i * 16 + lg;
        long base0 = (long)(b * SS + m0 + r0) * HD + h * DKH;
        long base1 = (long)(b * SS + m0 + r0 + 8) * HD + h * DKH;
        #pragma unroll
        for (int j = 0; j < 8; j++) {
            int c0 = nbase + j * 8 + lt * 2;
            *(__nv_bfloat162*)(ob + base0 + c0) =
                __floats2bfloat162_rn(acc[i][j][0], acc[i][j][1]);
            *(__nv_bfloat162*)(ob + base1 + c0) =
                __floats2bfloat162_rn(acc[i][j][2], acc[i][j][3]);
        }
    }
}

// ---------------- bf16 tensor-core GEMM, BK=64, 3-stage cp.async ----------
#define NSTAGE 3
#define BK 64
template<int BM, bool TB>
struct SmemCfg {
    static constexpr int AROW  = 72;                 // 64 + 8 pad
    static constexpr int BROWS = TB ? 128 : 64;
    static constexpr int BCOLS = TB ? 72 : 136;
    static constexpr int A_ELEMS = NSTAGE * BM * AROW;
    static constexpr int B_ELEMS = NSTAGE * BROWS * BCOLS;
    static constexpr int BYTES = (A_ELEMS + B_ELEMS) * 2;
};

template<int BM, bool TB, bool RELU, bool RES, bool OUTBF>
__global__ void __launch_bounds__(256)
gemm_bf(const __nv_bfloat16* __restrict__ A, const __nv_bfloat16* __restrict__ B,
        const float* __restrict__ bias, const float* __restrict__ res,
        float* __restrict__ Cf, __nv_bfloat16* __restrict__ Cb,
        int K, int lda, int ldb, int ldc,
        long sAb, long sAh, long sBb, long sBh, long sCb, long sCh)
{
    constexpr int IT = BM / 32;

    extern __shared__ __align__(16) char smem_raw[];
    __nv_bfloat16* As = (__nv_bfloat16*)smem_raw;
    __nv_bfloat16* Bs = As + SmemCfg<BM,TB>::A_ELEMS;

    int z = blockIdx.z;
    int bb = z >> 3, hh = z & 7;
    A += bb * sAb + hh * sAh;
    B += bb * sBb + hh * sBh;
    if (RES) res += bb * sCb + hh * sCh;
    long cbase = bb * sCb + hh * sCh;

    const int m0 = blockIdx.y * BM, n0 = blockIdx.x << 7;
    const int tid  = threadIdx.x;
    const int wid  = tid >> 5;
    const int lane = tid & 31;
    const int mbase = (wid >> 2) * (BM / 2);
    const int nbase = (wid & 3) * 32;
    const int lr  = ((lane >> 3) & 1) * 8 + (lane & 7);
    const int lc8 = (lane >> 4) * 8;

    uint32_t sAs = (uint32_t)__cvta_generic_to_shared(As);
    uint32_t sBs = (uint32_t)__cvta_generic_to_shared(Bs);

    float acc[IT][4][4];
    #pragma unroll
    for (int i = 0; i < IT; i++)
        #pragma unroll
        for (int j = 0; j < 4; j++)
            #pragma unroll
            for (int r = 0; r < 4; r++) acc[i][j][r] = 0.f;

    auto stage = [&](int s, int kb) {
        // A: BM rows x 64 k = BM*8 16B chunks
        #pragma unroll
        for (int t = 0; t < BM / 32; t++) {
            int idx = tid + t * 256;
            int row = idx >> 3, ck = idx & 7;
            uint32_t d = sAs + 2u * ((s * BM + row) * 72 + ck * 8);
            cpa16(d, A + (long)(m0 + row) * lda + kb + ck * 8);
        }
        if (!TB) {
            // B: 64 k-rows x 128 n = 64*16 chunks
            #pragma unroll
            for (int t = 0; t < 4; t++) {
                int idx = tid + t * 256;
                int row = idx >> 4, ck = idx & 15;
                uint32_t d = sBs + 2u * ((s * 64 + row) * 136 + ck * 8);
                cpa16(d, B + (long)(kb + row) * ldb + n0 + ck * 8);
            }
        } else {
            // B: 128 n-rows x 64 k = 128*8 chunks
            #pragma unroll
            for (int t = 0; t < 4; t++) {
                int idx = tid + t * 256;
                int row = idx >> 3, ck = idx & 7;
                uint32_t d = sBs + 2u * ((s * 128 + row) * 72 + ck * 8);
                cpa16(d, B + (long)(n0 + row) * ldb + kb + ck * 8);
            }
        }
    };

    const int NIT = K >> 6;       // all call sites K >= 512
    stage(0, 0);  cp_commit();
    stage(1, 64); cp_commit();

    for (int it = 0; it < NIT; it++) {
        int s = it % 3;
        cp_wait<1>();
        __syncthreads();

        #pragma unroll
        for (int ks = 0; ks < 64; ks += 16) {
            uint32_t a[IT][4], bf[4][2];
            #pragma unroll
            for (int i = 0; i < IT; i++) {
                uint32_t addr = sAs + 2u * ((s * BM + mbase + i * 16 + lr) * 72 + ks + lc8);
                ldsm4(a[i][0], a[i][1], a[i][2], a[i][3], addr);
            }
            #pragma unroll
            for (int jb = 0; jb < 2; jb++) {
                uint32_t r0, r1, r2, r3;
                if (!TB) {
                    uint32_t addr = sBs + 2u * ((s * 64 + ks + lr) * 136 + nbase + jb * 16 + lc8);
                    ldsm4t(r0, r1, r2, r3, addr);
                    bf[jb * 2 + 0][0] = r0; bf[jb * 2 + 0][1] = r1;
                    bf[jb * 2 + 1][0] = r2; bf[jb * 2 + 1][1] = r3;
                } else {
                    uint32_t addr = sBs + 2u * ((s * 128 + nbase + jb * 16 + lr) * 72 + ks + lc8);
                    ldsm4(r0, r1, r2, r3, addr);
                    bf[jb * 2 + 0][0] = r0; bf[jb * 2 + 0][1] = r2;
                    bf[jb * 2 + 1][0] = r1; bf[jb * 2 + 1][1] = r3;
                }
            }
            #pragma unroll
            for (int i = 0; i < IT; i++)
                #pragma unroll
                for (int j = 0; j < 4; j++)
                    mma_bf16(acc[i][j], a[i], bf[j]);
        }

        // stage (it+2)%3 == (it-1)%3: all warps passed the sync at top of
        // this iteration, so the (it-1) reads are complete -> safe.
        if (it + 2 < NIT) stage((it + 2) % 3, (it + 2) << 6);
        cp_commit();
    }

    #pragma unroll
    for (int i = 0; i < IT; i++) {
        int r0 = m0 + mbase + i * 16 + (lane >> 2);
        #pragma unroll
        for (int j = 0; j < 4; j++) {
            int c0 = n0 + nbase + j * 8 + (lane & 3) * 2;
            float b0 = 0.f, b1 = 0.f;
            if (bias) { b0 = bias[c0]; b1 = bias[c0 + 1]; }
            float v00 = acc[i][j][0] + b0, v01 = acc[i][j][1] + b1;
            float v10 = acc[i][j][2] + b0, v11 = acc[i][j][3] + b1;
            if (RELU) {
                v00 = fmaxf(v00, 0.f); v01 = fmaxf(v01, 0.f);
                v10 = fmaxf(v10, 0.f); v11 = fmaxf(v11, 0.f);
            }
            if (RES) {
                v00 += res[(long)r0 * ldc + c0];
                v01 += res[(long)r0 * ldc + c0 + 1];
                v10 += res[(long)(r0 + 8) * ldc + c0];
                v11 += res[(long)(r0 + 8) * ldc + c0 + 1];
            }
            if (OUTBF) {
                *(__nv_bfloat162*)(Cb + cbase + (long)r0 * ldc + c0) =
                    __floats2bfloat162_rn(v00, v01);
                *(__nv_bfloat162*)(Cb + cbase + (long)(r0 + 8) * ldc + c0) =
                    __floats2bfloat162_rn(v10, v11);
            } else {
                *(float2*)(Cf + cbase + (long)r0 * ldc + c0)       = make_float2(v00, v01);
                *(float2*)(Cf + cbase + (long)(r0 + 8) * ldc + c0) = make_float2(v10, v11);
            }
        }
    }
}

// ---------------------------------------------------------------------------
extern "C" void kernel_launch(void* const* d_in, const int* in_sizes, int n_in,
                              void* d_out, int out_size)
{
    const float* data    = (const float*)d_in[0];
    const int*   attn_m  = (const int*)  d_in[1];
    const int*   view    = (const int*)  d_in[2];
    const float* seg_emb = (const float*)d_in[3];
    const float* Wq = (const float*)d_in[4];
    const float* bq = (const float*)d_in[5];
    const float* Wk = (const float*)d_in[6];
    const float* bk = (const float*)d_in[7];
    const float* Wv = (const float*)d_in[8];
    const float* bv = (const float*)d_in[9];
    const float* Wo = (const float*)d_in[10];
    const float* bo = (const float*)d_in[11];
    const float* W1 = (const float*)d_in[12];
    const float* b1 = (const float*)d_in[13];
    const float* W2 = (const float*)d_in[14];
    const float* b2 = (const float*)d_in[15];
    const float* alpha1 = (const float*)d_in[16];
    const float* bias1  = (const float*)d_in[17];
    const float* alpha2 = (const float*)d_in[18];
    const float* bias2  = (const float*)d_in[19];
    const float* alpha_f = (const float*)d_in[20];
    const float* bias_f  = (const float*)d_in[21];
    float* out = (float*)d_out;

    float *x;
    __nv_bfloat16 *x2b, *qkv, *ob, *fb;
    __nv_bfloat16 *wqkv, *wo, *w1, *w2;
    float *bqkv;
    cudaGetSymbolAddress((void**)&x,    g_x);
    cudaGetSymbolAddress((void**)&x2b,  g_x2b);
    cudaGetSymbolAddress((void**)&qkv,  g_qkv);
    cudaGetSymbolAddress((void**)&ob,   g_ob);
    cudaGetSymbolAddress((void**)&fb,   g_fb);
    cudaGetSymbolAddress((void**)&wqkv, g_wqkv);
    cudaGetSymbolAddress((void**)&bqkv, g_bqkv);
    cudaGetSymbolAddress((void**)&wo,   g_wo);
    cudaGetSymbolAddress((void**)&w1,   g_w1);
    cudaGetSymbolAddress((void**)&w2,   g_w2);

    constexpr int SM_NN128 = SmemCfg<128,false>::BYTES;   // 107520
    constexpr int SM_NN64  = SmemCfg<64, false>::BYTES;   // 79872
    cudaFuncSetAttribute(gemm_bf<128,false,false,false,true>,
        cudaFuncAttributeMaxDynamicSharedMemorySize, SM_NN128);
    cudaFuncSetAttribute(gemm_bf<128,false,true,false,true>,
        cudaFuncAttributeMaxDynamicSharedMemorySize, SM_NN128);
    cudaFuncSetAttribute(gemm_bf<64,false,false,true,false>,
        cudaFuncAttributeMaxDynamicSharedMemorySize, SM_NN64);
    cudaFuncSetAttribute(attn_fused,
        cudaFuncAttributeMaxDynamicSharedMemorySize, ATT_SMEM_BYTES);

    cvt_weights<<<(6 * (WSZ / 4)) / 256, 256>>>(Wq, Wk, Wv, Wo, W1, W2);
    cvt_bias<<<(LNUM * QKVN + 255) / 256, 256>>>(bq, bk, bv);
    embed_kernel<<<(TOK * DMODEL + 255) / 256, 256>>>(data, seg_emb, view, x);

    for (int i = 0; i < LNUM; i++) {
        layernorm_kernel<true><<<TOK / 16, 256>>>(x, alpha1 + i * DMODEL, bias1 + i * DMODEL,
                                                  nullptr, x2b);

        // fused QKV: [2048,512] @ [512,6144]
        dim3 gp(QKVN / 128, TOK / 128, 1);
        gemm_bf<128,false,false,false,true><<<gp, 256, SM_NN128>>>(
            x2b, wqkv + (long)i * DMODEL * QKVN, bqkv + (long)i * QKVN,
            nullptr, nullptr, qkv, DMODEL, DMODEL, QKVN, QKVN, 0,0,0,0,0,0);

        // fused attention: scores + softmax + PV -> g_ob
        dim3 gs(SS / 128, BB * HEADS);
        attn_fused<<<gs, 256, ATT_SMEM_BYTES>>>(qkv, attn_m, ob);

        // x = x + o @ Wo + bo
        dim3 go(DMODEL / 128, TOK / 64, 1);
        gemm_bf<64,false,false,true,false><<<go, 256, SM_NN64>>>(
            ob, wo + (long)i * HD * DMODEL, bo + (long)i * DMODEL,
            x, x, nullptr, HD, HD, DMODEL, DMODEL, 0,0,0,0,0,0);

        layernorm_kernel<true><<<TOK / 16, 256>>>(x, alpha2 + i * DMODEL, bias2 + i * DMODEL,
                                                  nullptr, x2b);

        // ff = relu(x2 @ W1 + b1)
        dim3 gf(DFFN / 128, TOK / 128, 1);
        gemm_bf<128,false,true,false,true><<<gf, 256, SM_NN128>>>(
            x2b, w1 + (long)i * DMODEL * DFFN, b1 + (long)i * DFFN,
            nullptr, nullptr, fb, DMODEL, DMODEL, DFFN, DFFN, 0,0,0,0,0,0);

        // x = x + ff @ W2 + b2
        gemm_bf<64,false,false,true,false><<<go, 256, SM_NN64>>>(
            fb, w2 + (long)i * DFFN * DMODEL, b2 + (long)i * DMODEL,
            x, x, nullptr, DFFN, DFFN, DMODEL, DMODEL, 0,0,0,0,0,0);
    }

    layernorm_kernel<false><<<TOK / 16, 256>>>(x, alpha_f, bias_f, out, nullptr);
}